// round 3
// baseline (speedup 1.0000x reference)
#include <cuda_runtime.h>

#define BB 16
#define NN 25
#define WW 128
#define CH 256              // c*h
#define SS 3200             // n*w
#define BSTRIDE 819200
#define CSTRIDE 51200
#define NSTRIDE 2048

// Scratch. Device globals are zero-initialized once; att only ever writes
// the causally-reachable column groups of each row, the rest stay 0 forever
// (never written by any launch), which out_kernel relies on.
__device__ float g_p[BB*CH*CH];     // softmax probabilities, 4 MB
__device__ float g_invq[BB*CH];
__device__ float g_invk[BB*CH];

__device__ __forceinline__ int row_base(int b, int t) {
    return b*BSTRIDE + (t >> 4)*CSTRIDE + (t & 15)*WW;
}

// ---------------------------------------------------------------------------
// Kernel 1: per-row L2 norms of Q and K (rows of length 3200).
// ---------------------------------------------------------------------------
__global__ __launch_bounds__(256) void norms_kernel(const float* __restrict__ q,
                                                    const float* __restrict__ k) {
    int warp = threadIdx.x >> 5, lane = threadIdx.x & 31;
    int row = blockIdx.x * 8 + warp;
    int b = row >> 8, t = row & 255;
    int base = row_base(b, t) + lane * 4;
    float sq = 0.f, sk = 0.f;
    #pragma unroll
    for (int n = 0; n < NN; ++n) {
        const float4 qa = *(const float4*)(q + base + n*NSTRIDE);
        const float4 ka = *(const float4*)(k + base + n*NSTRIDE);
        sq += qa.x*qa.x + qa.y*qa.y + qa.z*qa.z + qa.w*qa.w;
        sk += ka.x*ka.x + ka.y*ka.y + ka.z*ka.z + ka.w*ka.w;
    }
    #pragma unroll
    for (int o = 16; o; o >>= 1) {
        sq += __shfl_xor_sync(0xffffffffu, sq, o);
        sk += __shfl_xor_sync(0xffffffffu, sk, o);
    }
    if (lane == 0) {
        g_invq[row] = 1.f / fmaxf(sqrtf(sq), 1e-12f);
        g_invk[row] = 1.f / fmaxf(sqrtf(sk), 1e-12f);
    }
}

// ---------------------------------------------------------------------------
// Kernel 2: att = Qn @ Kn^T, causal mask, softmax -> g_p.
// CTA = paired 16-row tiles (a0=16*tt, b0=240-16*tt). Each warp owns rows
// {a0+2w, a0+2w+1, b0+2w, b0+2w+1}: per-warp work 8*(ja+jb) ~= const -> no
// barrier imbalance. Columns tx+32*j; j bounded per row-pair (warp-uniform
// runtime loop bounds -> real branch skip, not predication).
// ---------------------------------------------------------------------------
#define SC 32
#define KPAD 36
__global__ __launch_bounds__(256) void att_kernel(const float* __restrict__ q,
                                                  const float* __restrict__ k) {
    __shared__ float Qs[32*KPAD];
    __shared__ float Ks[CH*KPAD];

    const int tt = blockIdx.x & 7, b = blockIdx.x >> 3;
    const int a0 = tt*16, b0 = 240 - tt*16;
    const int tid = threadIdx.x;
    const int tx = tid & 31, w = tid >> 5;
    const int jm_a = (a0 + 2*w + 1) >> 5;   // max active j for A-pair rows
    const int jm_b = (b0 + 2*w + 1) >> 5;   // max active j for B-pair rows (>= jm_a)

    float acc[4][8];
    #pragma unroll
    for (int i = 0; i < 4; ++i)
        #pragma unroll
        for (int j = 0; j < 8; ++j) acc[i][j] = 0.f;

    // loaders: thread loads float4 at (local row = tid/8, s-offset = (tid%8)*4)
    const int lrow = tid >> 3, l8 = (tid & 7) * 4;
    const int qrow_abs = (lrow < 16) ? a0 + lrow : b0 + (lrow - 16);
    const int qbase = row_base(b, qrow_abs) + l8;
    int kbase[8];
    #pragma unroll
    for (int g = 0; g < 8; ++g) kbase[g] = row_base(b, lrow + 32*g) + l8;

    const int r0l = 2*w, r1l = 2*w + 1, r2l = 16 + 2*w, r3l = 17 + 2*w;

    for (int s0 = 0; s0 < SS; s0 += SC) {
        const int off = (s0 >> 7) * NSTRIDE + (s0 & 127);
        *(float4*)&Qs[lrow*KPAD + l8] = *(const float4*)(q + qbase + off);
        #pragma unroll
        for (int g = 0; g < 8; ++g)
            *(float4*)&Ks[(lrow + 32*g)*KPAD + l8] = *(const float4*)(k + kbase[g] + off);
        __syncthreads();

        #pragma unroll 8
        for (int s4 = 0; s4 < SC; s4 += 4) {
            const float4 q0 = *(const float4*)&Qs[r0l*KPAD + s4];
            const float4 q1 = *(const float4*)&Qs[r1l*KPAD + s4];
            const float4 q2 = *(const float4*)&Qs[r2l*KPAD + s4];
            const float4 q3 = *(const float4*)&Qs[r3l*KPAD + s4];
            int j = 0;
            for (; j <= jm_a; ++j) {
                const float4 kv = *(const float4*)&Ks[(tx + 32*j)*KPAD + s4];
                acc[0][j] += q0.x*kv.x + q0.y*kv.y + q0.z*kv.z + q0.w*kv.w;
                acc[1][j] += q1.x*kv.x + q1.y*kv.y + q1.z*kv.z + q1.w*kv.w;
                acc[2][j] += q2.x*kv.x + q2.y*kv.y + q2.z*kv.z + q2.w*kv.w;
                acc[3][j] += q3.x*kv.x + q3.y*kv.y + q3.z*kv.z + q3.w*kv.w;
            }
            for (; j <= jm_b; ++j) {
                const float4 kv = *(const float4*)&Ks[(tx + 32*j)*KPAD + s4];
                acc[2][j] += q2.x*kv.x + q2.y*kv.y + q2.z*kv.z + q2.w*kv.w;
                acc[3][j] += q3.x*kv.x + q3.y*kv.y + q3.z*kv.z + q3.w*kv.w;
            }
        }
        __syncthreads();
    }

    // epilogue: scale by inverse norms, causal mask, softmax (row in one warp)
    const int bb = b * CH;
    float ik[8];
    #pragma unroll
    for (int j = 0; j < 8; ++j) if (j <= jm_b) ik[j] = g_invk[bb + tx + 32*j];

    #pragma unroll
    for (int i = 0; i < 4; ++i) {
        const int trow = ((i < 2) ? a0 : (b0 - 16)) + 16*(i & 2)/2 + 2*w + (i & 1);
        // i=0,1 -> a0+2w+(i&1) ; i=2,3 -> b0+2w+(i&1)
        const int row2 = (i < 2) ? (a0 + 2*w + (i & 1)) : (b0 + 2*w + (i & 1));
        const int jm = (i < 2) ? jm_a : jm_b;
        const float iq = g_invq[bb + row2];
        float vals[8], e[8];
        float m = -1e30f;
        #pragma unroll
        for (int j = 0; j < 8; ++j) {
            if (j <= jm) {
                const int cc = tx + 32*j;
                vals[j] = (cc <= row2) ? acc[i][j] * iq * ik[j] : -1e30f;
                m = fmaxf(m, vals[j]);
            }
        }
        #pragma unroll
        for (int o = 16; o; o >>= 1) m = fmaxf(m, __shfl_xor_sync(0xffffffffu, m, o));

        float ssum = 0.f;
        #pragma unroll
        for (int j = 0; j < 8; ++j) {
            if (j <= jm) {
                const int cc = tx + 32*j;
                e[j] = (cc <= row2) ? __expf(vals[j] - m) : 0.f;
                ssum += e[j];
            }
        }
        #pragma unroll
        for (int o = 16; o; o >>= 1) ssum += __shfl_xor_sync(0xffffffffu, ssum, o);

        const float inv = 1.f / ssum;
        float* prow = g_p + (bb + row2)*CH;
        #pragma unroll
        for (int j = 0; j < 8; ++j)
            if (j <= jm) prow[tx + 32*j] = e[j] * inv;
        (void)trow;
    }
}

// ---------------------------------------------------------------------------
// Kernel 3: out = P @ V + token_v with causal r-bound.
// CTA = 64(t) x 128(w) tile for one (b, tt4, n): r-loop runs to t0+64 only.
// Thread (tx,ty): rows t0+ty*8+i (i<8), cols w=tx*4. Heavy tiles first.
// ---------------------------------------------------------------------------
#define OPAD 36
__global__ __launch_bounds__(256) void out_kernel(const float* __restrict__ v,
                                                  float* __restrict__ out) {
    __shared__ float Ps[64*OPAD];    // [t local][r local]
    __shared__ float Vs[32*WW];      // [r local][w]

    const int n   = blockIdx.x % NN;
    const int tmp = blockIdx.x / NN;
    const int tt  = 3 - (tmp & 3);          // heavy (tt=3) first
    const int b   = tmp >> 2;
    const int t0  = tt * 64;
    const int nr  = t0 + 64;                // causal bound on r
    const int tid = threadIdx.x, tx = tid & 31, ty = tid >> 5;
    const int bb  = b * CH;

    float4 acc[8];
    #pragma unroll
    for (int i = 0; i < 8; ++i) acc[i] = make_float4(0.f, 0.f, 0.f, 0.f);

    for (int rc0 = 0; rc0 < nr; rc0 += 32) {
        // P tile: 64 rows x 32 r (512 float4 quads, 2 per thread)
        #pragma unroll
        for (int p = 0; p < 2; ++p) {
            const int idx = p*256 + tid;            // 0..511
            const int prow = idx >> 3;              // 0..63
            const int pq   = (idx & 7) * 4;         // 0..28
            *(float4*)&Ps[prow*OPAD + pq] =
                *(const float4*)&g_p[(bb + t0 + prow)*CH + rc0 + pq];
        }
        // V tile: 32 r x 128 w (1024 quads, 4 per thread)
        #pragma unroll
        for (int p = 0; p < 4; ++p) {
            const int idx = p*256 + tid;            // 0..1023
            const int r   = idx >> 5;               // 0..31
            const int wq  = (idx & 31) * 4;         // 0..124
            *(float4*)&Vs[r*WW + wq] =
                *(const float4*)(v + row_base(b, rc0 + r) + n*NSTRIDE + wq);
        }
        __syncthreads();

        #pragma unroll 8
        for (int r = 0; r < 32; ++r) {
            const float4 vv = *(const float4*)&Vs[r*WW + tx*4];
            #pragma unroll
            for (int i = 0; i < 8; ++i) {
                const float pp = Ps[(ty*8 + i)*OPAD + r];
                acc[i].x += pp * vv.x;
                acc[i].y += pp * vv.y;
                acc[i].z += pp * vv.z;
                acc[i].w += pp * vv.w;
            }
        }
        __syncthreads();
    }

    #pragma unroll
    for (int i = 0; i < 8; ++i) {
        const int t = t0 + ty*8 + i;
        const int a = row_base(b, t) + n*NSTRIDE + tx*4;
        const float4 bu = *(const float4*)(v + a);
        const float4 o = make_float4(acc[i].x + bu.x, acc[i].y + bu.y,
                                     acc[i].z + bu.z, acc[i].w + bu.w);
        *(float4*)(out + a) = o;
    }
}

// ---------------------------------------------------------------------------
extern "C" void kernel_launch(void* const* d_in, const int* in_sizes, int n_in,
                              void* d_out, int out_size) {
    const float* q = (const float*)d_in[0];
    const float* k = (const float*)d_in[1];
    const float* v = (const float*)d_in[2];
    float* out = (float*)d_out;

    norms_kernel<<<BB*CH/8, 256>>>(q, k);
    att_kernel<<<BB*8, 256>>>(q, k);
    out_kernel<<<BB*4*NN, 256>>>(v, out);
}

// round 5
// speedup vs baseline: 5.1544x; 5.1544x over previous
#include <cuda_runtime.h>
#include <cuda_bf16.h>
#include <cstdint>

#define BB 16
#define NN 25
#define WW 128
#define CH 256              // c*h
#define SS 3200             // n*w
#define BSTRIDE 819200
#define CSTRIDE 51200
#define NSTRIDE 2048
#define KCH 5               // K-split chunks in att

// Scratch (device globals). Zero-init relied upon: g_att_part tiles for the
// fully-masked (mh0,nh1) region are never written by any launch -> stay 0.
__device__ float g_att_part[KCH*BB*CH*CH];        // 21 MB partial logits
__device__ __nv_bfloat16 g_qb[BB*CH*SS];          // normalized Q bf16 [row][s]
__device__ __nv_bfloat16 g_kb[BB*CH*SS];          // normalized K bf16 [row][s]
__device__ __nv_bfloat16 g_vt[(size_t)BB*SS*CH];  // V^T bf16 [b][s][r]
__device__ __nv_bfloat16 g_pb[BB*CH*CH];          // P bf16, zeros above diag

__device__ __forceinline__ int row_base(int b, int t) {
    return b*BSTRIDE + (t >> 4)*CSTRIDE + (t & 15)*WW;
}

#define SW128(x) ((x) ^ (((x) >> 3) & 0x70))

__device__ __forceinline__ uint32_t smem_u32(const void* p) {
    uint32_t a;
    asm("{ .reg .u64 t; cvta.to.shared.u64 t, %1; cvt.u32.u64 %0, t; }" : "=r"(a) : "l"(p));
    return a;
}
__device__ __forceinline__ void ldsm_x4(uint32_t& r0, uint32_t& r1,
                                        uint32_t& r2, uint32_t& r3, uint32_t addr) {
    asm volatile("ldmatrix.sync.aligned.m8n8.x4.shared.b16 {%0,%1,%2,%3}, [%4];"
                 : "=r"(r0), "=r"(r1), "=r"(r2), "=r"(r3) : "r"(addr));
}
__device__ __forceinline__ void mma16816(float* c, const uint32_t* a,
                                         uint32_t b0, uint32_t b1) {
    asm volatile(
        "mma.sync.aligned.m16n8k16.row.col.f32.bf16.bf16.f32 "
        "{%0,%1,%2,%3}, {%4,%5,%6,%7}, {%8,%9}, {%0,%1,%2,%3};"
        : "+f"(c[0]), "+f"(c[1]), "+f"(c[2]), "+f"(c[3])
        : "r"(a[0]), "r"(a[1]), "r"(a[2]), "r"(a[3]), "r"(b0), "r"(b1));
}
__device__ __forceinline__ uint32_t b2u(__nv_bfloat162 h) {
    return *reinterpret_cast<uint32_t*>(&h);
}

// One 64-wide K chunk of a 128x128 warp-tiled GEMM.
// smem A/B: 128 rows x 64 bf16, SW128-swizzled 128B rows.
// Warp wid: m0=(wid&3)*32, n0=(wid>>2)*64. Accum c[2 mt][8 n8][4].
__device__ __forceinline__ void mma_chunk(uint32_t aSm, uint32_t bSm,
                                          int m0, int n0, int lane,
                                          float c[2][8][4]) {
    const int lar = lane & 15;
    const int lak = (lane >> 4) * 16;
    const int lbr = (lane & 7) | ((lane >> 4) << 3);
    const int lbk = ((lane >> 3) & 1) * 16;
    #pragma unroll
    for (int ks = 0; ks < 4; ++ks) {
        const int kb = ks * 32;
        uint32_t a[2][4];
        #pragma unroll
        for (int mt = 0; mt < 2; ++mt)
            ldsm_x4(a[mt][0], a[mt][1], a[mt][2], a[mt][3],
                    aSm + SW128((uint32_t)((m0 + mt*16 + lar)*128 + kb + lak)));
        #pragma unroll
        for (int np = 0; np < 4; ++np) {
            uint32_t b0, b1, b2, b3;
            ldsm_x4(b0, b1, b2, b3,
                    bSm + SW128((uint32_t)((n0 + np*16 + lbr)*128 + kb + lbk)));
            mma16816(c[0][np*2    ], a[0], b0, b1);
            mma16816(c[0][np*2 + 1], a[0], b2, b3);
            mma16816(c[1][np*2    ], a[1], b0, b1);
            mma16816(c[1][np*2 + 1], a[1], b2, b3);
        }
    }
}

// ---------------------------------------------------------------------------
// Kernel 1: fused L2-norm + normalize + bf16 pack for Q and K.
// One CTA (160 thr) per (b,t) row of 3200.
// ---------------------------------------------------------------------------
__global__ __launch_bounds__(160) void prep_qk(const float* __restrict__ q,
                                               const float* __restrict__ k) {
    __shared__ float rq[8], rk[8];
    const int row = blockIdx.x;
    const int b = row >> 8, t = row & 255;
    const int tid = threadIdx.x, lane = tid & 31, w = tid >> 5;
    const int base = row_base(b, t);
    float4 qv[5], kv[5];
    float sq = 0.f, sk = 0.f;
    #pragma unroll
    for (int g = 0; g < 5; ++g) {
        const int s = (tid + 160*g) * 4;
        const int a = base + (s >> 7)*NSTRIDE + (s & 127);
        qv[g] = *(const float4*)(q + a);
        kv[g] = *(const float4*)(k + a);
        sq += qv[g].x*qv[g].x + qv[g].y*qv[g].y + qv[g].z*qv[g].z + qv[g].w*qv[g].w;
        sk += kv[g].x*kv[g].x + kv[g].y*kv[g].y + kv[g].z*kv[g].z + kv[g].w*kv[g].w;
    }
    #pragma unroll
    for (int o = 16; o; o >>= 1) {
        sq += __shfl_xor_sync(0xffffffffu, sq, o);
        sk += __shfl_xor_sync(0xffffffffu, sk, o);
    }
    if (lane == 0) { rq[w] = sq; rk[w] = sk; }
    __syncthreads();
    sq = rq[0] + rq[1] + rq[2] + rq[3] + rq[4];
    sk = rk[0] + rk[1] + rk[2] + rk[3] + rk[4];
    const float iq = 1.f / fmaxf(sqrtf(sq), 1e-12f);
    const float ik = 1.f / fmaxf(sqrtf(sk), 1e-12f);
    #pragma unroll
    for (int g = 0; g < 5; ++g) {
        const int s = (tid + 160*g) * 4;
        uint2 uq, uk;
        uq.x = b2u(__floats2bfloat162_rn(qv[g].x*iq, qv[g].y*iq));
        uq.y = b2u(__floats2bfloat162_rn(qv[g].z*iq, qv[g].w*iq));
        uk.x = b2u(__floats2bfloat162_rn(kv[g].x*ik, kv[g].y*ik));
        uk.y = b2u(__floats2bfloat162_rn(kv[g].z*ik, kv[g].w*ik));
        *(uint2*)(g_qb + (size_t)row*SS + s) = uq;
        *(uint2*)(g_kb + (size_t)row*SS + s) = uk;
    }
}

// ---------------------------------------------------------------------------
// Kernel 2: Vt[b][s][r] = bf16(V[b][r][s]). 64x64 tiles.
// ---------------------------------------------------------------------------
__global__ __launch_bounds__(256) void vt_kernel(const float* __restrict__ v) {
    __shared__ float T[64][65];
    int bx = blockIdx.x;                 // b*200 + rt*50 + st
    const int b = bx / 200; bx %= 200;
    const int rt = bx / 50, st = bx % 50;
    const int r0 = rt*64, s0 = st*64;
    const int tid = threadIdx.x;
    const int rl = tid >> 2, qq = tid & 3;
    const int off = (s0 >> 7)*NSTRIDE + (s0 & 127);
    const int ga = row_base(b, r0 + rl) + off + qq*16;
    #pragma unroll
    for (int g = 0; g < 4; ++g) {
        const float4 d = *(const float4*)(v + ga + g*4);
        T[rl][qq*16 + g*4 + 0] = d.x;
        T[rl][qq*16 + g*4 + 1] = d.y;
        T[rl][qq*16 + g*4 + 2] = d.z;
        T[rl][qq*16 + g*4 + 3] = d.w;
    }
    __syncthreads();
    const int sl = tid >> 2, qr = tid & 3;
    __align__(16) __nv_bfloat16 o[16];
    #pragma unroll
    for (int e = 0; e < 16; ++e) o[e] = __float2bfloat16(T[qr*16 + e][sl]);
    uint4* dst = (uint4*)(g_vt + (size_t)(b*SS + s0 + sl)*256 + r0 + qr*16);
    dst[0] = ((uint4*)o)[0];
    dst[1] = ((uint4*)o)[1];
}

// ---------------------------------------------------------------------------
// Kernel 3: att partial logits, bf16 mma.sync. CTA = (kc, b, tile) with
// tile in {(mh0,nh0),(mh1,nh0),(mh1,nh1)} (fully-masked tile skipped).
// M=128, N=128, K=640 in 10 chunks of 64 through swizzled smem.
// ---------------------------------------------------------------------------
__global__ __launch_bounds__(256) void att_mma() {
    __shared__ __align__(128) char sA[16384];
    __shared__ __align__(128) char sB[16384];
    int idx = blockIdx.x;
    const int kc = idx / 48; idx %= 48;
    const int b = idx / 3, tt = idx % 3;
    const int t0  = (tt > 0)  ? 128 : 0;
    const int n0c = (tt == 2) ? 128 : 0;
    const int tid = threadIdx.x, lane = tid & 31, wid = tid >> 5;
    const int m0 = (wid & 3) * 32, n0w = (wid >> 2) * 64;
    const uint32_t aSm = smem_u32(sA), bSm = smem_u32(sB);

    float c[2][8][4];
    #pragma unroll
    for (int i = 0; i < 2; ++i)
        #pragma unroll
        for (int j = 0; j < 8; ++j)
            #pragma unroll
            for (int e = 0; e < 4; ++e) c[i][j][e] = 0.f;

    const int row = tid >> 1, hf = tid & 1;
    const __nv_bfloat16* qp = g_qb + (size_t)(b*256 + t0  + row)*SS;
    const __nv_bfloat16* kp = g_kb + (size_t)(b*256 + n0c + row)*SS;
    uint32_t so[4];
    #pragma unroll
    for (int g = 0; g < 4; ++g) so[g] = SW128((uint32_t)(row*128 + hf*64 + g*16));

    uint4 qa[4], ka[4];
    #pragma unroll
    for (int g = 0; g < 4; ++g) {
        qa[g] = *(const uint4*)(qp + kc*640 + hf*32 + g*8);
        ka[g] = *(const uint4*)(kp + kc*640 + hf*32 + g*8);
    }
    for (int it = 0; it < 10; ++it) {
        if (it) __syncthreads();             // prior compute done
        #pragma unroll
        for (int g = 0; g < 4; ++g) {
            *(uint4*)(sA + so[g]) = qa[g];
            *(uint4*)(sB + so[g]) = ka[g];
        }
        __syncthreads();
        if (it < 9) {
            const int s = kc*640 + (it + 1)*64 + hf*32;
            #pragma unroll
            for (int g = 0; g < 4; ++g) {
                qa[g] = *(const uint4*)(qp + s + g*8);
                ka[g] = *(const uint4*)(kp + s + g*8);
            }
        }
        mma_chunk(aSm, bSm, m0, n0w, lane, c);
    }

    float* dst = g_att_part + (size_t)kc*(4096*256) + (size_t)(b*256 + t0)*256;
    const int r0 = m0 + (lane >> 2);
    const int c0 = n0c + n0w + (lane & 3)*2;
    #pragma unroll
    for (int mt = 0; mt < 2; ++mt)
        #pragma unroll
        for (int n8 = 0; n8 < 8; ++n8) {
            float* p = dst + (size_t)(r0 + mt*16)*256 + c0 + n8*8;
            *(float2*)p           = make_float2(c[mt][n8][0], c[mt][n8][1]);
            *(float2*)(p + 8*256) = make_float2(c[mt][n8][2], c[mt][n8][3]);
        }
}

// ---------------------------------------------------------------------------
// Kernel 4: reduce partials, causal mask, softmax, emit P bf16.
// ---------------------------------------------------------------------------
__global__ __launch_bounds__(256) void softmax_kernel() {
    const int wid = threadIdx.x >> 5, lane = threadIdx.x & 31;
    const int row = blockIdx.x*8 + wid;   // b*256 + t
    const int t = row & 255;
    float a[8];
    #pragma unroll
    for (int j = 0; j < 8; ++j) {
        float s = 0.f;
        #pragma unroll
        for (int p = 0; p < KCH; ++p)
            s += g_att_part[(size_t)p*(4096*256) + (size_t)row*256 + lane + 32*j];
        a[j] = s;
    }
    float m = -1e30f;
    #pragma unroll
    for (int j = 0; j < 8; ++j) {
        const int cc = lane + 32*j;
        a[j] = (cc <= t) ? a[j] : -1e30f;
        m = fmaxf(m, a[j]);
    }
    #pragma unroll
    for (int o = 16; o; o >>= 1) m = fmaxf(m, __shfl_xor_sync(0xffffffffu, m, o));
    float s = 0.f, e[8];
    #pragma unroll
    for (int j = 0; j < 8; ++j) {
        const int cc = lane + 32*j;
        e[j] = (cc <= t) ? __expf(a[j] - m) : 0.f;
        s += e[j];
    }
    #pragma unroll
    for (int o = 16; o; o >>= 1) s += __shfl_xor_sync(0xffffffffu, s, o);
    const float inv = 1.f / s;
    #pragma unroll
    for (int j = 0; j < 8; ++j)
        g_pb[(size_t)row*256 + lane + 32*j] = __float2bfloat16(e[j]*inv);
}

// ---------------------------------------------------------------------------
// Kernel 5: out = P @ Vt^T + buffer. CTA = (b, mh, st): M=128 t, N=128 s,
// K=256 r (2 chunks for mh=0, P zero beyond). Grid 800.
// ---------------------------------------------------------------------------
__global__ __launch_bounds__(256) void out_mma(const float* __restrict__ v,
                                               float* __restrict__ out) {
    __shared__ __align__(128) char sA[16384];
    __shared__ __align__(128) char sB[16384];
    int idx = blockIdx.x;
    const int b = idx / 50; idx %= 50;
    const int mh = idx / 25, st = idx % 25;
    const int t0 = mh*128, s0 = st*128;
    const int nch = mh ? 4 : 2;
    const int tid = threadIdx.x, lane = tid & 31, wid = tid >> 5;
    const int m0 = (wid & 3) * 32, n0w = (wid >> 2) * 64;
    const uint32_t aSm = smem_u32(sA), bSm = smem_u32(sB);

    float c[2][8][4];
    #pragma unroll
    for (int i = 0; i < 2; ++i)
        #pragma unroll
        for (int j = 0; j < 8; ++j)
            #pragma unroll
            for (int e = 0; e < 4; ++e) c[i][j][e] = 0.f;

    const int row = tid >> 1, hf = tid & 1;
    const __nv_bfloat16* ap = g_pb + (size_t)(b*256  + t0 + row)*256;
    const __nv_bfloat16* bp = g_vt + (size_t)(b*3200 + s0 + row)*256;
    uint32_t so[4];
    #pragma unroll
    for (int g = 0; g < 4; ++g) so[g] = SW128((uint32_t)(row*128 + hf*64 + g*16));

    uint4 pa[4], va[4];
    #pragma unroll
    for (int g = 0; g < 4; ++g) {
        pa[g] = *(const uint4*)(ap + hf*32 + g*8);
        va[g] = *(const uint4*)(bp + hf*32 + g*8);
    }
    for (int ic = 0; ic < nch; ++ic) {
        if (ic) __syncthreads();
        #pragma unroll
        for (int g = 0; g < 4; ++g) {
            *(uint4*)(sA + so[g]) = pa[g];
            *(uint4*)(sB + so[g]) = va[g];
        }
        __syncthreads();
        if (ic + 1 < nch) {
            const int rc = (ic + 1)*64 + hf*32;
            #pragma unroll
            for (int g = 0; g < 4; ++g) {
                pa[g] = *(const uint4*)(ap + rc + g*8);
                va[g] = *(const uint4*)(bp + rc + g*8);
            }
        }
        mma_chunk(aSm, bSm, m0, n0w, lane, c);
    }

    const int r0 = m0 + (lane >> 2);
    const int sc0 = n0w + (lane & 3)*2;
    const int soff = (s0 >> 7)*NSTRIDE;
    #pragma unroll
    for (int mt = 0; mt < 2; ++mt) {
        const int tA = t0 + r0 + mt*16;
        const int gA = row_base(b, tA)     + soff;
        const int gB = row_base(b, tA + 8) + soff;
        #pragma unroll
        for (int n8 = 0; n8 < 8; ++n8) {
            const int sc = sc0 + n8*8;
            const float2 buA = *(const float2*)(v + gA + sc);
            const float2 buB = *(const float2*)(v + gB + sc);
            *(float2*)(out + gA + sc) =
                make_float2(c[mt][n8][0] + buA.x, c[mt][n8][1] + buA.y);
            *(float2*)(out + gB + sc) =
                make_float2(c[mt][n8][2] + buB.x, c[mt][n8][3] + buB.y);
        }
    }
}

// ---------------------------------------------------------------------------
extern "C" void kernel_launch(void* const* d_in, const int* in_sizes, int n_in,
                              void* d_out, int out_size) {
    const float* q = (const float*)d_in[0];
    const float* k = (const float*)d_in[1];
    const float* v = (const float*)d_in[2];
    float* out = (float*)d_out;

    prep_qk<<<BB*CH, 160>>>(q, k);
    vt_kernel<<<BB*200, 256>>>(v);
    att_mma<<<KCH*BB*3, 256>>>();
    softmax_kernel<<<BB*CH/8, 256>>>();
    out_mma<<<BB*50, 256>>>(v, out);
}

// round 6
// speedup vs baseline: 5.3784x; 1.0435x over previous
#include <cuda_runtime.h>
#include <cuda_fp16.h>
#include <cstdint>

#define BB 16
#define NN 25
#define WW 128
#define CH 256              // c*h
#define SS 3200             // n*w
#define BSTRIDE 819200
#define CSTRIDE 51200
#define NSTRIDE 2048
#define KCH 3               // K-split chunks in att (17/17/16 x 64)

// Scratch (device globals). Zero-init relied upon: g_att_part tiles for the
// fully-masked (mh0,nh1) region are never written by any launch -> stay 0.
__device__ float g_att_part[KCH*BB*CH*CH];        // 12.6 MB partial logits
__device__ __half g_qh[BB*CH*SS];                 // normalized Q fp16 [row][s]
__device__ __half g_kh[BB*CH*SS];                 // normalized K fp16 [row][s]
__device__ __half g_vt[(size_t)BB*SS*CH];         // V^T fp16 [b][s][r]
__device__ __half g_ph[BB*CH*CH];                 // P fp16, zeros above diag

__device__ __forceinline__ int row_base(int b, int t) {
    return b*BSTRIDE + (t >> 4)*CSTRIDE + (t & 15)*WW;
}

#define SW128(x) ((x) ^ (((x) >> 3) & 0x70))

__device__ __forceinline__ uint32_t smem_u32(const void* p) {
    uint32_t a;
    asm("{ .reg .u64 t; cvta.to.shared.u64 t, %1; cvt.u32.u64 %0, t; }" : "=r"(a) : "l"(p));
    return a;
}
__device__ __forceinline__ void ldsm_x4(uint32_t& r0, uint32_t& r1,
                                        uint32_t& r2, uint32_t& r3, uint32_t addr) {
    asm volatile("ldmatrix.sync.aligned.m8n8.x4.shared.b16 {%0,%1,%2,%3}, [%4];"
                 : "=r"(r0), "=r"(r1), "=r"(r2), "=r"(r3) : "r"(addr));
}
__device__ __forceinline__ void mma16816(float* c, const uint32_t* a,
                                         uint32_t b0, uint32_t b1) {
    asm volatile(
        "mma.sync.aligned.m16n8k16.row.col.f32.f16.f16.f32 "
        "{%0,%1,%2,%3}, {%4,%5,%6,%7}, {%8,%9}, {%0,%1,%2,%3};"
        : "+f"(c[0]), "+f"(c[1]), "+f"(c[2]), "+f"(c[3])
        : "r"(a[0]), "r"(a[1]), "r"(a[2]), "r"(a[3]), "r"(b0), "r"(b1));
}
__device__ __forceinline__ uint32_t h2u(__half2 h) {
    return *reinterpret_cast<uint32_t*>(&h);
}

// One 64-wide K chunk of a 128x128 warp-tiled GEMM.
// smem A/B: 128 rows x 64 fp16, SW128-swizzled 128B rows.
// Warp wid: m0=(wid&3)*32, n0=(wid>>2)*64. Accum c[2 mt][8 n8][4].
__device__ __forceinline__ void mma_chunk(uint32_t aSm, uint32_t bSm,
                                          int m0, int n0, int lane,
                                          float c[2][8][4]) {
    const int lar = lane & 15;
    const int lak = (lane >> 4) * 16;
    const int lbr = (lane & 7) | ((lane >> 4) << 3);
    const int lbk = ((lane >> 3) & 1) * 16;
    #pragma unroll
    for (int ks = 0; ks < 4; ++ks) {
        const int kb = ks * 32;
        uint32_t a[2][4];
        #pragma unroll
        for (int mt = 0; mt < 2; ++mt)
            ldsm_x4(a[mt][0], a[mt][1], a[mt][2], a[mt][3],
                    aSm + SW128((uint32_t)((m0 + mt*16 + lar)*128 + kb + lak)));
        #pragma unroll
        for (int np = 0; np < 4; ++np) {
            uint32_t b0, b1, b2, b3;
            ldsm_x4(b0, b1, b2, b3,
                    bSm + SW128((uint32_t)((n0 + np*16 + lbr)*128 + kb + lbk)));
            mma16816(c[0][np*2    ], a[0], b0, b1);
            mma16816(c[0][np*2 + 1], a[0], b2, b3);
            mma16816(c[1][np*2    ], a[1], b0, b1);
            mma16816(c[1][np*2 + 1], a[1], b2, b3);
        }
    }
}

// ---------------------------------------------------------------------------
// Kernel 1: fused L2-norm + normalize + fp16 pack for Q and K.
// ---------------------------------------------------------------------------
__global__ __launch_bounds__(160) void prep_qk(const float* __restrict__ q,
                                               const float* __restrict__ k) {
    __shared__ float rq[8], rk[8];
    const int row = blockIdx.x;
    const int b = row >> 8, t = row & 255;
    const int tid = threadIdx.x, lane = tid & 31, w = tid >> 5;
    const int base = row_base(b, t);
    float4 qv[5], kv[5];
    float sq = 0.f, sk = 0.f;
    #pragma unroll
    for (int g = 0; g < 5; ++g) {
        const int s = (tid + 160*g) * 4;
        const int a = base + (s >> 7)*NSTRIDE + (s & 127);
        qv[g] = *(const float4*)(q + a);
        kv[g] = *(const float4*)(k + a);
        sq += qv[g].x*qv[g].x + qv[g].y*qv[g].y + qv[g].z*qv[g].z + qv[g].w*qv[g].w;
        sk += kv[g].x*kv[g].x + kv[g].y*kv[g].y + kv[g].z*kv[g].z + kv[g].w*kv[g].w;
    }
    #pragma unroll
    for (int o = 16; o; o >>= 1) {
        sq += __shfl_xor_sync(0xffffffffu, sq, o);
        sk += __shfl_xor_sync(0xffffffffu, sk, o);
    }
    if (lane == 0) { rq[w] = sq; rk[w] = sk; }
    __syncthreads();
    sq = rq[0] + rq[1] + rq[2] + rq[3] + rq[4];
    sk = rk[0] + rk[1] + rk[2] + rk[3] + rk[4];
    const float iq = 1.f / fmaxf(sqrtf(sq), 1e-12f);
    const float ik = 1.f / fmaxf(sqrtf(sk), 1e-12f);
    #pragma unroll
    for (int g = 0; g < 5; ++g) {
        const int s = (tid + 160*g) * 4;
        uint2 uq, uk;
        uq.x = h2u(__floats2half2_rn(qv[g].x*iq, qv[g].y*iq));
        uq.y = h2u(__floats2half2_rn(qv[g].z*iq, qv[g].w*iq));
        uk.x = h2u(__floats2half2_rn(kv[g].x*ik, kv[g].y*ik));
        uk.y = h2u(__floats2half2_rn(kv[g].z*ik, kv[g].w*ik));
        *(uint2*)(g_qh + (size_t)row*SS + s) = uq;
        *(uint2*)(g_kh + (size_t)row*SS + s) = uk;
    }
}

// ---------------------------------------------------------------------------
// Kernel 2: Vt[b][s][r] = fp16(V[b][r][s]). 64x64 tiles.
// ---------------------------------------------------------------------------
__global__ __launch_bounds__(256) void vt_kernel(const float* __restrict__ v) {
    __shared__ float T[64][65];
    int bx = blockIdx.x;                 // b*200 + rt*50 + st
    const int b = bx / 200; bx %= 200;
    const int rt = bx / 50, st = bx % 50;
    const int r0 = rt*64, s0 = st*64;
    const int tid = threadIdx.x;
    const int rl = tid >> 2, qq = tid & 3;
    const int off = (s0 >> 7)*NSTRIDE + (s0 & 127);
    const int ga = row_base(b, r0 + rl) + off + qq*16;
    #pragma unroll
    for (int g = 0; g < 4; ++g) {
        const float4 d = *(const float4*)(v + ga + g*4);
        T[rl][qq*16 + g*4 + 0] = d.x;
        T[rl][qq*16 + g*4 + 1] = d.y;
        T[rl][qq*16 + g*4 + 2] = d.z;
        T[rl][qq*16 + g*4 + 3] = d.w;
    }
    __syncthreads();
    const int sl = tid >> 2, qr = tid & 3;
    __align__(16) __half o[16];
    #pragma unroll
    for (int e = 0; e < 16; ++e) o[e] = __float2half(T[qr*16 + e][sl]);
    uint4* dst = (uint4*)(g_vt + (size_t)(b*SS + s0 + sl)*256 + r0 + qr*16);
    dst[0] = ((uint4*)o)[0];
    dst[1] = ((uint4*)o)[1];
}

// ---------------------------------------------------------------------------
// Kernel 3: att partial logits, fp16 mma.sync, double-buffered smem.
// CTA = (kc, b, tile), tile in {(mh0,nh0),(mh1,nh0),(mh1,nh1)}.
// M=128, N=128, K = 17/17/16 chunks of 64. Grid 144 (~1 resident wave).
// ---------------------------------------------------------------------------
__global__ __launch_bounds__(256) void att_mma() {
    __shared__ __align__(128) char sA[2][16384];
    __shared__ __align__(128) char sB[2][16384];
    int idx = blockIdx.x;
    const int kc = idx / 48; idx %= 48;
    const int b = idx / 3, tt = idx % 3;
    const int t0  = (tt > 0)  ? 128 : 0;
    const int n0c = (tt == 2) ? 128 : 0;
    const int nch = (kc == 2) ? 16 : 17;
    const int sb  = kc * 17 * 64;
    const int tid = threadIdx.x, lane = tid & 31, wid = tid >> 5;
    const int m0 = (wid & 3) * 32, n0w = (wid >> 2) * 64;

    float c[2][8][4];
    #pragma unroll
    for (int i = 0; i < 2; ++i)
        #pragma unroll
        for (int j = 0; j < 8; ++j)
            #pragma unroll
            for (int e = 0; e < 4; ++e) c[i][j][e] = 0.f;

    const int row = tid >> 1, hf = tid & 1;
    const __half* qp = g_qh + (size_t)(b*256 + t0  + row)*SS + sb + hf*32;
    const __half* kp = g_kh + (size_t)(b*256 + n0c + row)*SS + sb + hf*32;
    uint32_t so[4];
    #pragma unroll
    for (int g = 0; g < 4; ++g) so[g] = SW128((uint32_t)(row*128 + hf*64 + g*16));

    uint4 qa[4], ka[4];
    #pragma unroll
    for (int g = 0; g < 4; ++g) {
        qa[g] = *(const uint4*)(qp + g*8);
        ka[g] = *(const uint4*)(kp + g*8);
    }
    #pragma unroll
    for (int g = 0; g < 4; ++g) {
        *(uint4*)(sA[0] + so[g]) = qa[g];
        *(uint4*)(sB[0] + so[g]) = ka[g];
    }
    __syncthreads();

    for (int it = 0; it < nch; ++it) {
        const int nxt = it + 1;
        if (nxt < nch) {
            #pragma unroll
            for (int g = 0; g < 4; ++g) {
                qa[g] = *(const uint4*)(qp + nxt*64 + g*8);
                ka[g] = *(const uint4*)(kp + nxt*64 + g*8);
            }
        }
        mma_chunk(smem_u32(sA[it & 1]), smem_u32(sB[it & 1]), m0, n0w, lane, c);
        if (nxt < nch) {
            #pragma unroll
            for (int g = 0; g < 4; ++g) {
                *(uint4*)(sA[nxt & 1] + so[g]) = qa[g];
                *(uint4*)(sB[nxt & 1] + so[g]) = ka[g];
            }
        }
        __syncthreads();
    }

    float* dst = g_att_part + (size_t)kc*(4096*256) + (size_t)(b*256 + t0)*256;
    const int r0 = m0 + (lane >> 2);
    const int c0 = n0c + n0w + (lane & 3)*2;
    #pragma unroll
    for (int mt = 0; mt < 2; ++mt)
        #pragma unroll
        for (int n8 = 0; n8 < 8; ++n8) {
            float* p = dst + (size_t)(r0 + mt*16)*256 + c0 + n8*8;
            *(float2*)p           = make_float2(c[mt][n8][0], c[mt][n8][1]);
            *(float2*)(p + 8*256) = make_float2(c[mt][n8][2], c[mt][n8][3]);
        }
}

// ---------------------------------------------------------------------------
// Kernel 4: reduce partials, causal mask, softmax, emit P fp16.
// ---------------------------------------------------------------------------
__global__ __launch_bounds__(256) void softmax_kernel() {
    const int wid = threadIdx.x >> 5, lane = threadIdx.x & 31;
    const int row = blockIdx.x*8 + wid;   // b*256 + t
    const int t = row & 255;
    float a[8];
    #pragma unroll
    for (int j = 0; j < 8; ++j) {
        float s = 0.f;
        #pragma unroll
        for (int p = 0; p < KCH; ++p)
            s += g_att_part[(size_t)p*(4096*256) + (size_t)row*256 + lane + 32*j];
        a[j] = s;
    }
    float m = -1e30f;
    #pragma unroll
    for (int j = 0; j < 8; ++j) {
        const int cc = lane + 32*j;
        a[j] = (cc <= t) ? a[j] : -1e30f;
        m = fmaxf(m, a[j]);
    }
    #pragma unroll
    for (int o = 16; o; o >>= 1) m = fmaxf(m, __shfl_xor_sync(0xffffffffu, m, o));
    float s = 0.f, e[8];
    #pragma unroll
    for (int j = 0; j < 8; ++j) {
        const int cc = lane + 32*j;
        e[j] = (cc <= t) ? __expf(a[j] - m) : 0.f;
        s += e[j];
    }
    #pragma unroll
    for (int o = 16; o; o >>= 1) s += __shfl_xor_sync(0xffffffffu, s, o);
    const float inv = 1.f / s;
    #pragma unroll
    for (int j = 0; j < 8; ++j)
        g_ph[(size_t)row*256 + lane + 32*j] = __float2half(e[j]*inv);
}

// ---------------------------------------------------------------------------
// Kernel 5: out = P @ Vt^T + buffer, double-buffered. CTA = (b, mh, st):
// M=128 t, N=128 s, K = 2 chunks (mh=0) or 4 (mh=1). Grid 800.
// ---------------------------------------------------------------------------
__global__ __launch_bounds__(256) void out_mma(const float* __restrict__ v,
                                               float* __restrict__ out) {
    __shared__ __align__(128) char sA[2][16384];
    __shared__ __align__(128) char sB[2][16384];
    int idx = blockIdx.x;
    const int b = idx / 50; idx %= 50;
    const int mh = idx / 25, st = idx % 25;
    const int t0 = mh*128, s0 = st*128;
    const int nch = mh ? 4 : 2;
    const int tid = threadIdx.x, lane = tid & 31, wid = tid >> 5;
    const int m0 = (wid & 3) * 32, n0w = (wid >> 2) * 64;

    float c[2][8][4];
    #pragma unroll
    for (int i = 0; i < 2; ++i)
        #pragma unroll
        for (int j = 0; j < 8; ++j)
            #pragma unroll
            for (int e = 0; e < 4; ++e) c[i][j][e] = 0.f;

    const int row = tid >> 1, hf = tid & 1;
    const __half* ap = g_ph + (size_t)(b*256  + t0 + row)*256 + hf*32;
    const __half* bp = g_vt + (size_t)(b*3200 + s0 + row)*256 + hf*32;
    uint32_t so[4];
    #pragma unroll
    for (int g = 0; g < 4; ++g) so[g] = SW128((uint32_t)(row*128 + hf*64 + g*16));

    uint4 pa[4], va[4];
    #pragma unroll
    for (int g = 0; g < 4; ++g) {
        pa[g] = *(const uint4*)(ap + g*8);
        va[g] = *(const uint4*)(bp + g*8);
    }
    #pragma unroll
    for (int g = 0; g < 4; ++g) {
        *(uint4*)(sA[0] + so[g]) = pa[g];
        *(uint4*)(sB[0] + so[g]) = va[g];
    }
    __syncthreads();

    for (int ic = 0; ic < nch; ++ic) {
        const int nxt = ic + 1;
        if (nxt < nch) {
            #pragma unroll
            for (int g = 0; g < 4; ++g) {
                pa[g] = *(const uint4*)(ap + nxt*64 + g*8);
                va[g] = *(const uint4*)(bp + nxt*64 + g*8);
            }
        }
        mma_chunk(smem_u32(sA[ic & 1]), smem_u32(sB[ic & 1]), m0, n0w, lane, c);
        if (nxt < nch) {
            #pragma unroll
            for (int g = 0; g < 4; ++g) {
                *(uint4*)(sA[nxt & 1] + so[g]) = pa[g];
                *(uint4*)(sB[nxt & 1] + so[g]) = va[g];
            }
        }
        __syncthreads();
    }

    const int r0 = m0 + (lane >> 2);
    const int sc0 = n0w + (lane & 3)*2;
    const int soff = (s0 >> 7)*NSTRIDE;
    #pragma unroll
    for (int mt = 0; mt < 2; ++mt) {
        const int tA = t0 + r0 + mt*16;
        const int gA = row_base(b, tA)     + soff;
        const int gB = row_base(b, tA + 8) + soff;
        #pragma unroll
        for (int n8 = 0; n8 < 8; ++n8) {
            const int sc = sc0 + n8*8;
            const float2 buA = *(const float2*)(v + gA + sc);
            const float2 buB = *(const float2*)(v + gB + sc);
            *(float2*)(out + gA + sc) =
                make_float2(c[mt][n8][0] + buA.x, c[mt][n8][1] + buA.y);
            *(float2*)(out + gB + sc) =
                make_float2(c[mt][n8][2] + buB.x, c[mt][n8][3] + buB.y);
        }
    }
}

// ---------------------------------------------------------------------------
extern "C" void kernel_launch(void* const* d_in, const int* in_sizes, int n_in,
                              void* d_out, int out_size) {
    const float* q = (const float*)d_in[0];
    const float* k = (const float*)d_in[1];
    const float* v = (const float*)d_in[2];
    float* out = (float*)d_out;

    prep_qk<<<BB*CH, 160>>>(q, k);
    vt_kernel<<<BB*200, 256>>>(v);
    att_mma<<<KCH*BB*3, 256>>>();
    softmax_kernel<<<BB*CH/8, 256>>>();
    out_mma<<<BB*50, 256>>>(v, out);
}

// round 7
// speedup vs baseline: 5.7774x; 1.0742x over previous
#include <cuda_runtime.h>
#include <cuda_fp16.h>
#include <cstdint>

#define BB 16
#define NN 25
#define WW 128
#define CH 256              // c*h
#define SS 3200             // n*w
#define BSTRIDE 819200
#define CSTRIDE 51200
#define NSTRIDE 2048
#define KCH 3               // K-split chunks in att (17/17/16 x 64)

// Scratch (device globals). Zero-init relied upon: g_att_part tiles for the
// fully-masked (mh0,nh1) region are never written by any launch -> stay 0.
__device__ float g_att_part[KCH*BB*CH*CH];        // 12.6 MB partial logits
__device__ __half g_qh[BB*CH*SS];                 // normalized Q fp16 [row][s]
__device__ __half g_kh[BB*CH*SS];                 // normalized K fp16 [row][s]
__device__ __half g_ph[BB*CH*CH];                 // P fp16, zeros above diag

__device__ __forceinline__ int row_base(int b, int t) {
    return b*BSTRIDE + (t >> 4)*CSTRIDE + (t & 15)*WW;
}

#define SW128(x) ((x) ^ (((x) >> 3) & 0x70))

__device__ __forceinline__ uint32_t smem_u32(const void* p) {
    uint32_t a;
    asm("{ .reg .u64 t; cvta.to.shared.u64 t, %1; cvt.u32.u64 %0, t; }" : "=r"(a) : "l"(p));
    return a;
}
__device__ __forceinline__ void ldsm_x4(uint32_t& r0, uint32_t& r1,
                                        uint32_t& r2, uint32_t& r3, uint32_t addr) {
    asm volatile("ldmatrix.sync.aligned.m8n8.x4.shared.b16 {%0,%1,%2,%3}, [%4];"
                 : "=r"(r0), "=r"(r1), "=r"(r2), "=r"(r3) : "r"(addr));
}
__device__ __forceinline__ void ldsm_x4t(uint32_t& r0, uint32_t& r1,
                                         uint32_t& r2, uint32_t& r3, uint32_t addr) {
    asm volatile("ldmatrix.sync.aligned.m8n8.x4.trans.shared.b16 {%0,%1,%2,%3}, [%4];"
                 : "=r"(r0), "=r"(r1), "=r"(r2), "=r"(r3) : "r"(addr));
}
__device__ __forceinline__ void mma16816(float* c, const uint32_t* a,
                                         uint32_t b0, uint32_t b1) {
    asm volatile(
        "mma.sync.aligned.m16n8k16.row.col.f32.f16.f16.f32 "
        "{%0,%1,%2,%3}, {%4,%5,%6,%7}, {%8,%9}, {%0,%1,%2,%3};"
        : "+f"(c[0]), "+f"(c[1]), "+f"(c[2]), "+f"(c[3])
        : "r"(a[0]), "r"(a[1]), "r"(a[2]), "r"(a[3]), "r"(b0), "r"(b1));
}
__device__ __forceinline__ uint32_t h2u(__half2 h) {
    return *reinterpret_cast<uint32_t*>(&h);
}

// One 64-wide K chunk, both operands SW128-swizzled [row][64 halves].
__device__ __forceinline__ void mma_chunk(uint32_t aSm, uint32_t bSm,
                                          int m0, int n0, int lane,
                                          float c[2][8][4]) {
    const int lar = lane & 15;
    const int lak = (lane >> 4) * 16;
    const int lbr = (lane & 7) | ((lane >> 4) << 3);
    const int lbk = ((lane >> 3) & 1) * 16;
    #pragma unroll
    for (int ks = 0; ks < 4; ++ks) {
        const int kb = ks * 32;
        uint32_t a[2][4];
        #pragma unroll
        for (int mt = 0; mt < 2; ++mt)
            ldsm_x4(a[mt][0], a[mt][1], a[mt][2], a[mt][3],
                    aSm + SW128((uint32_t)((m0 + mt*16 + lar)*128 + kb + lak)));
        #pragma unroll
        for (int np = 0; np < 4; ++np) {
            uint32_t b0, b1, b2, b3;
            ldsm_x4(b0, b1, b2, b3,
                    bSm + SW128((uint32_t)((n0 + np*16 + lbr)*128 + kb + lbk)));
            mma16816(c[0][np*2    ], a[0], b0, b1);
            mma16816(c[0][np*2 + 1], a[0], b2, b3);
            mma16816(c[1][np*2    ], a[1], b0, b1);
            mma16816(c[1][np*2 + 1], a[1], b2, b3);
        }
    }
}

// One 64-deep K chunk where B (= V) sits naturally [r=k 64 rows][s=n 128 halves],
// row stride 136 halves (272B = 17*16B -> conflict-free LDSM, no swizzle).
// B fragments fetched via ldmatrix.trans.
#define VSTR 136
__device__ __forceinline__ void mma_chunk_bt(uint32_t aSm, uint32_t vSm,
                                             int m0, int n0, int lane,
                                             float c[2][8][4]) {
    const int lar = lane & 15;
    const int lak = (lane >> 4) * 16;
    const int vr = lane & 15;
    const int vs = (lane >> 4) * 8;
    #pragma unroll
    for (int ks = 0; ks < 4; ++ks) {
        uint32_t a[2][4];
        #pragma unroll
        for (int mt = 0; mt < 2; ++mt)
            ldsm_x4(a[mt][0], a[mt][1], a[mt][2], a[mt][3],
                    aSm + SW128((uint32_t)((m0 + mt*16 + lar)*128 + ks*32 + lak)));
        #pragma unroll
        for (int np = 0; np < 4; ++np) {
            uint32_t b0, b1, b2, b3;
            ldsm_x4t(b0, b1, b2, b3,
                     vSm + (uint32_t)((ks*16 + vr)*(VSTR*2) + (n0 + np*16 + vs)*2));
            mma16816(c[0][np*2    ], a[0], b0, b1);
            mma16816(c[0][np*2 + 1], a[0], b2, b3);
            mma16816(c[1][np*2    ], a[1], b0, b1);
            mma16816(c[1][np*2 + 1], a[1], b2, b3);
        }
    }
}

// ---------------------------------------------------------------------------
// Kernel 1: fused L2-norm + normalize + fp16 pack for Q and K.
// ---------------------------------------------------------------------------
__global__ __launch_bounds__(160) void prep_qk(const float* __restrict__ q,
                                               const float* __restrict__ k) {
    __shared__ float rq[8], rk[8];
    const int row = blockIdx.x;
    const int b = row >> 8, t = row & 255;
    const int tid = threadIdx.x, lane = tid & 31, w = tid >> 5;
    const int base = row_base(b, t);
    float4 qv[5], kv[5];
    float sq = 0.f, sk = 0.f;
    #pragma unroll
    for (int g = 0; g < 5; ++g) {
        const int s = (tid + 160*g) * 4;
        const int a = base + (s >> 7)*NSTRIDE + (s & 127);
        qv[g] = *(const float4*)(q + a);
        kv[g] = *(const float4*)(k + a);
        sq += qv[g].x*qv[g].x + qv[g].y*qv[g].y + qv[g].z*qv[g].z + qv[g].w*qv[g].w;
        sk += kv[g].x*kv[g].x + kv[g].y*kv[g].y + kv[g].z*kv[g].z + kv[g].w*kv[g].w;
    }
    #pragma unroll
    for (int o = 16; o; o >>= 1) {
        sq += __shfl_xor_sync(0xffffffffu, sq, o);
        sk += __shfl_xor_sync(0xffffffffu, sk, o);
    }
    if (lane == 0) { rq[w] = sq; rk[w] = sk; }
    __syncthreads();
    sq = rq[0] + rq[1] + rq[2] + rq[3] + rq[4];
    sk = rk[0] + rk[1] + rk[2] + rk[3] + rk[4];
    const float iq = 1.f / fmaxf(sqrtf(sq), 1e-12f);
    const float ik = 1.f / fmaxf(sqrtf(sk), 1e-12f);
    #pragma unroll
    for (int g = 0; g < 5; ++g) {
        const int s = (tid + 160*g) * 4;
        uint2 uq, uk;
        uq.x = h2u(__floats2half2_rn(qv[g].x*iq, qv[g].y*iq));
        uq.y = h2u(__floats2half2_rn(qv[g].z*iq, qv[g].w*iq));
        uk.x = h2u(__floats2half2_rn(kv[g].x*ik, kv[g].y*ik));
        uk.y = h2u(__floats2half2_rn(kv[g].z*ik, kv[g].w*ik));
        *(uint2*)(g_qh + (size_t)row*SS + s) = uq;
        *(uint2*)(g_kh + (size_t)row*SS + s) = uk;
    }
}

// ---------------------------------------------------------------------------
// Kernel 2: att partial logits, fp16 mma.sync, double-buffered smem.
// CTA = (kc, b, tile), tile in {(mh0,nh0),(mh1,nh0),(mh1,nh1)}. Grid 144.
// ---------------------------------------------------------------------------
__global__ __launch_bounds__(256) void att_mma() {
    __shared__ __align__(128) char sA[2][16384];
    __shared__ __align__(128) char sB[2][16384];
    int idx = blockIdx.x;
    const int kc = idx / 48; idx %= 48;
    const int b = idx / 3, tt = idx % 3;
    const int t0  = (tt > 0)  ? 128 : 0;
    const int n0c = (tt == 2) ? 128 : 0;
    const int nch = (kc == 2) ? 16 : 17;
    const int sb  = kc * 17 * 64;
    const int tid = threadIdx.x, lane = tid & 31, wid = tid >> 5;
    const int m0 = (wid & 3) * 32, n0w = (wid >> 2) * 64;

    float c[2][8][4];
    #pragma unroll
    for (int i = 0; i < 2; ++i)
        #pragma unroll
        for (int j = 0; j < 8; ++j)
            #pragma unroll
            for (int e = 0; e < 4; ++e) c[i][j][e] = 0.f;

    const int row = tid >> 1, hf = tid & 1;
    const __half* qp = g_qh + (size_t)(b*256 + t0  + row)*SS + sb + hf*32;
    const __half* kp = g_kh + (size_t)(b*256 + n0c + row)*SS + sb + hf*32;
    uint32_t so[4];
    #pragma unroll
    for (int g = 0; g < 4; ++g) so[g] = SW128((uint32_t)(row*128 + hf*64 + g*16));

    uint4 qa[4], ka[4];
    #pragma unroll
    for (int g = 0; g < 4; ++g) {
        qa[g] = *(const uint4*)(qp + g*8);
        ka[g] = *(const uint4*)(kp + g*8);
    }
    #pragma unroll
    for (int g = 0; g < 4; ++g) {
        *(uint4*)(sA[0] + so[g]) = qa[g];
        *(uint4*)(sB[0] + so[g]) = ka[g];
    }
    __syncthreads();

    for (int it = 0; it < nch; ++it) {
        const int nxt = it + 1;
        if (nxt < nch) {
            #pragma unroll
            for (int g = 0; g < 4; ++g) {
                qa[g] = *(const uint4*)(qp + nxt*64 + g*8);
                ka[g] = *(const uint4*)(kp + nxt*64 + g*8);
            }
        }
        mma_chunk(smem_u32(sA[it & 1]), smem_u32(sB[it & 1]), m0, n0w, lane, c);
        if (nxt < nch) {
            #pragma unroll
            for (int g = 0; g < 4; ++g) {
                *(uint4*)(sA[nxt & 1] + so[g]) = qa[g];
                *(uint4*)(sB[nxt & 1] + so[g]) = ka[g];
            }
        }
        __syncthreads();
    }

    float* dst = g_att_part + (size_t)kc*(4096*256) + (size_t)(b*256 + t0)*256;
    const int r0 = m0 + (lane >> 2);
    const int c0 = n0c + n0w + (lane & 3)*2;
    #pragma unroll
    for (int mt = 0; mt < 2; ++mt)
        #pragma unroll
        for (int n8 = 0; n8 < 8; ++n8) {
            float* p = dst + (size_t)(r0 + mt*16)*256 + c0 + n8*8;
            *(float2*)p           = make_float2(c[mt][n8][0], c[mt][n8][1]);
            *(float2*)(p + 8*256) = make_float2(c[mt][n8][2], c[mt][n8][3]);
        }
}

// ---------------------------------------------------------------------------
// Kernel 3: reduce partials (float4 vectorized), mask, softmax, emit P fp16.
// Warp per row; lane covers cols 4*(j2*32+lane)+e.
// ---------------------------------------------------------------------------
__global__ __launch_bounds__(256) void softmax_kernel() {
    const int wid = threadIdx.x >> 5, lane = threadIdx.x & 31;
    const int row = blockIdx.x*8 + wid;   // b*256 + t
    const int t = row & 255;
    float4 a[2];
    #pragma unroll
    for (int j2 = 0; j2 < 2; ++j2) {
        float4 s = make_float4(0.f, 0.f, 0.f, 0.f);
        #pragma unroll
        for (int p = 0; p < KCH; ++p) {
            const float4 d = *(const float4*)(g_att_part + (size_t)p*(4096*256)
                                              + (size_t)row*256 + (j2*32 + lane)*4);
            s.x += d.x; s.y += d.y; s.z += d.z; s.w += d.w;
        }
        a[j2] = s;
    }
    float m = -1e30f;
    #pragma unroll
    for (int j2 = 0; j2 < 2; ++j2) {
        const int c0 = (j2*32 + lane)*4;
        float* e = &a[j2].x;
        #pragma unroll
        for (int q = 0; q < 4; ++q) {
            e[q] = (c0 + q <= t) ? e[q] : -1e30f;
            m = fmaxf(m, e[q]);
        }
    }
    #pragma unroll
    for (int o = 16; o; o >>= 1) m = fmaxf(m, __shfl_xor_sync(0xffffffffu, m, o));
    float ssum = 0.f;
    #pragma unroll
    for (int j2 = 0; j2 < 2; ++j2) {
        const int c0 = (j2*32 + lane)*4;
        float* e = &a[j2].x;
        #pragma unroll
        for (int q = 0; q < 4; ++q) {
            e[q] = (c0 + q <= t) ? __expf(e[q] - m) : 0.f;
            ssum += e[q];
        }
    }
    #pragma unroll
    for (int o = 16; o; o >>= 1) ssum += __shfl_xor_sync(0xffffffffu, ssum, o);
    const float inv = 1.f / ssum;
    #pragma unroll
    for (int j2 = 0; j2 < 2; ++j2) {
        uint2 u;
        u.x = h2u(__floats2half2_rn(a[j2].x*inv, a[j2].y*inv));
        u.y = h2u(__floats2half2_rn(a[j2].z*inv, a[j2].w*inv));
        *(uint2*)(g_ph + (size_t)row*256 + (j2*32 + lane)*4) = u;
    }
}

// ---------------------------------------------------------------------------
// Kernel 4: out = P @ V^T + buffer. CTA = (b, mh, st): M=128 t, N=128 s
// (s-tile = exactly one n-block -> contiguous gmem), K = 128/256 r.
// V staged fp32->fp16 inline, natural [r][s]; B frags via ldmatrix.trans.
// ---------------------------------------------------------------------------
__global__ __launch_bounds__(256) void out_mma(const float* __restrict__ v,
                                               float* __restrict__ out) {
    __shared__ __align__(128) char sA[2][16384];          // P 128t x 64r halves
    __shared__ __align__(128) char sV[2][64*VSTR*2];      // V 64r x 128s halves
    int idx = blockIdx.x;
    const int b = idx / 50; idx %= 50;
    const int mh = idx / 25, st = idx % 25;
    const int t0 = mh*128;
    const int nch = mh ? 4 : 2;
    const int tid = threadIdx.x, lane = tid & 31, wid = tid >> 5;
    const int m0 = (wid & 3) * 32, n0w = (wid >> 2) * 64;

    float c[2][8][4];
    #pragma unroll
    for (int i = 0; i < 2; ++i)
        #pragma unroll
        for (int j = 0; j < 8; ++j)
            #pragma unroll
            for (int e = 0; e < 4; ++e) c[i][j][e] = 0.f;

    // P staging: row = tid/2, halves hf*32 within 64-chunk
    const int row = tid >> 1, hf = tid & 1;
    const __half* ap = g_ph + (size_t)(b*256 + t0 + row)*256 + hf*32;
    uint32_t soA[4];
    #pragma unroll
    for (int g = 0; g < 4; ++g) soA[g] = SW128((uint32_t)(row*128 + hf*64 + g*16));

    // V staging: row rl = tid/4 (0..63), s-range qs = (tid&3)*32
    const int rl = tid >> 2, qs = (tid & 3) * 32;
    const int vbase = row_base(b, rl) + st*NSTRIDE + qs;   // + ic*4*CSTRIDE per chunk
    const uint32_t vso = (uint32_t)(rl*(VSTR*2) + qs*2);

    uint4 pa[4];
    float4 va[8];
    #pragma unroll
    for (int g = 0; g < 4; ++g) pa[g] = *(const uint4*)(ap + g*8);
    #pragma unroll
    for (int g = 0; g < 8; ++g) va[g] = *(const float4*)(v + vbase + g*4);
    #pragma unroll
    for (int g = 0; g < 4; ++g) *(uint4*)(sA[0] + soA[g]) = pa[g];
    #pragma unroll
    for (int g = 0; g < 4; ++g) {
        uint4 u;
        u.x = h2u(__floats2half2_rn(va[2*g].x,   va[2*g].y));
        u.y = h2u(__floats2half2_rn(va[2*g].z,   va[2*g].w));
        u.z = h2u(__floats2half2_rn(va[2*g+1].x, va[2*g+1].y));
        u.w = h2u(__floats2half2_rn(va[2*g+1].z, va[2*g+1].w));
        *(uint4*)(sV[0] + vso + g*16) = u;
    }
    __syncthreads();

    for (int ic = 0; ic < nch; ++ic) {
        const int nxt = ic + 1;
        if (nxt < nch) {
            #pragma unroll
            for (int g = 0; g < 4; ++g) pa[g] = *(const uint4*)(ap + nxt*64 + g*8);
            #pragma unroll
            for (int g = 0; g < 8; ++g)
                va[g] = *(const float4*)(v + vbase + nxt*4*CSTRIDE + g*4);
        }
        mma_chunk_bt(smem_u32(sA[ic & 1]), smem_u32(sV[ic & 1]), m0, n0w, lane, c);
        if (nxt < nch) {
            #pragma unroll
            for (int g = 0; g < 4; ++g) *(uint4*)(sA[nxt & 1] + soA[g]) = pa[g];
            #pragma unroll
            for (int g = 0; g < 4; ++g) {
                uint4 u;
                u.x = h2u(__floats2half2_rn(va[2*g].x,   va[2*g].y));
                u.y = h2u(__floats2half2_rn(va[2*g].z,   va[2*g].w));
                u.z = h2u(__floats2half2_rn(va[2*g+1].x, va[2*g+1].y));
                u.w = h2u(__floats2half2_rn(va[2*g+1].z, va[2*g+1].w));
                *(uint4*)(sV[nxt & 1] + vso + g*16) = u;
            }
        }
        __syncthreads();
    }

    const int r0 = m0 + (lane >> 2);
    const int sc0 = n0w + (lane & 3)*2;
    const int soff = st*NSTRIDE;
    #pragma unroll
    for (int mt = 0; mt < 2; ++mt) {
        const int tA = t0 + r0 + mt*16;
        const int gA = row_base(b, tA)     + soff;
        const int gB = row_base(b, tA + 8) + soff;
        #pragma unroll
        for (int n8 = 0; n8 < 8; ++n8) {
            const int sc = sc0 + n8*8;
            const float2 buA = *(const float2*)(v + gA + sc);
            const float2 buB = *(const float2*)(v + gB + sc);
            *(float2*)(out + gA + sc) =
                make_float2(c[mt][n8][0] + buA.x, c[mt][n8][1] + buA.y);
            *(float2*)(out + gB + sc) =
                make_float2(c[mt][n8][2] + buB.x, c[mt][n8][3] + buB.y);
        }
    }
}

// ---------------------------------------------------------------------------
extern "C" void kernel_launch(void* const* d_in, const int* in_sizes, int n_in,
                              void* d_out, int out_size) {
    const float* q = (const float*)d_in[0];
    const float* k = (const float*)d_in[1];
    const float* v = (const float*)d_in[2];
    float* out = (float*)d_out;

    prep_qk<<<BB*CH, 160>>>(q, k);
    att_mma<<<KCH*BB*3, 256>>>();
    softmax_kernel<<<BB*CH/8, 256>>>();
    out_mma<<<BB*50, 256>>>(v, out);
}

// round 8
// speedup vs baseline: 6.1829x; 1.0702x over previous
#include <cuda_runtime.h>
#include <cuda_fp16.h>
#include <cstdint>

#define BB 16
#define NN 25
#define WW 128
#define CH 256              // c*h
#define SS 3200             // n*w
#define BSTRIDE 819200
#define CSTRIDE 51200
#define NSTRIDE 2048
#define KCH 3               // K-split chunks in att (17/17/16 x 64)

// Scratch (device globals). Zero-init relied upon: g_att_part tiles for the
// fully-masked (mh0,nh1) region are never written by any launch -> stay 0.
__device__ float g_att_part[KCH*BB*CH*CH];        // 12.6 MB partial logits
__device__ __half g_qh[BB*CH*SS];                 // normalized Q fp16 [row][s]
__device__ __half g_kh[BB*CH*SS];                 // normalized K fp16 [row][s]
__device__ __half g_ph[BB*CH*CH];                 // P fp16, zeros above diag

__device__ __forceinline__ int row_base(int b, int t) {
    return b*BSTRIDE + (t >> 4)*CSTRIDE + (t & 15)*WW;
}

#define SW128(x) ((x) ^ (((x) >> 3) & 0x70))

__device__ __forceinline__ uint32_t smem_u32(const void* p) {
    uint32_t a;
    asm("{ .reg .u64 t; cvta.to.shared.u64 t, %1; cvt.u32.u64 %0, t; }" : "=r"(a) : "l"(p));
    return a;
}
__device__ __forceinline__ void cp16(uint32_t dst, const void* src) {
    asm volatile("cp.async.cg.shared.global [%0], [%1], 16;"
                 :: "r"(dst), "l"(__cvta_generic_to_global(src)));
}
#define CP_COMMIT() asm volatile("cp.async.commit_group;" ::: "memory")
#define CP_WAIT0()  asm volatile("cp.async.wait_group 0;" ::: "memory")

__device__ __forceinline__ void ldsm_x4(uint32_t& r0, uint32_t& r1,
                                        uint32_t& r2, uint32_t& r3, uint32_t addr) {
    asm volatile("ldmatrix.sync.aligned.m8n8.x4.shared.b16 {%0,%1,%2,%3}, [%4];"
                 : "=r"(r0), "=r"(r1), "=r"(r2), "=r"(r3) : "r"(addr));
}
__device__ __forceinline__ void ldsm_x4t(uint32_t& r0, uint32_t& r1,
                                         uint32_t& r2, uint32_t& r3, uint32_t addr) {
    asm volatile("ldmatrix.sync.aligned.m8n8.x4.trans.shared.b16 {%0,%1,%2,%3}, [%4];"
                 : "=r"(r0), "=r"(r1), "=r"(r2), "=r"(r3) : "r"(addr));
}
__device__ __forceinline__ void mma16816(float* c, const uint32_t* a,
                                         uint32_t b0, uint32_t b1) {
    asm volatile(
        "mma.sync.aligned.m16n8k16.row.col.f32.f16.f16.f32 "
        "{%0,%1,%2,%3}, {%4,%5,%6,%7}, {%8,%9}, {%0,%1,%2,%3};"
        : "+f"(c[0]), "+f"(c[1]), "+f"(c[2]), "+f"(c[3])
        : "r"(a[0]), "r"(a[1]), "r"(a[2]), "r"(a[3]), "r"(b0), "r"(b1));
}
__device__ __forceinline__ uint32_t h2u(__half2 h) {
    return *reinterpret_cast<uint32_t*>(&h);
}

// One 64-wide K chunk, both operands SW128-swizzled [row][64 halves].
__device__ __forceinline__ void mma_chunk(uint32_t aSm, uint32_t bSm,
                                          int m0, int n0, int lane,
                                          float c[2][8][4]) {
    const int lar = lane & 15;
    const int lak = (lane >> 4) * 16;
    const int lbr = (lane & 7) | ((lane >> 4) << 3);
    const int lbk = ((lane >> 3) & 1) * 16;
    #pragma unroll
    for (int ks = 0; ks < 4; ++ks) {
        const int kb = ks * 32;
        uint32_t a[2][4];
        #pragma unroll
        for (int mt = 0; mt < 2; ++mt)
            ldsm_x4(a[mt][0], a[mt][1], a[mt][2], a[mt][3],
                    aSm + SW128((uint32_t)((m0 + mt*16 + lar)*128 + kb + lak)));
        #pragma unroll
        for (int np = 0; np < 4; ++np) {
            uint32_t b0, b1, b2, b3;
            ldsm_x4(b0, b1, b2, b3,
                    bSm + SW128((uint32_t)((n0 + np*16 + lbr)*128 + kb + lbk)));
            mma16816(c[0][np*2    ], a[0], b0, b1);
            mma16816(c[0][np*2 + 1], a[0], b2, b3);
            mma16816(c[1][np*2    ], a[1], b0, b1);
            mma16816(c[1][np*2 + 1], a[1], b2, b3);
        }
    }
}

// One 64-deep K chunk; B (= V) natural [r=k 64 rows][s=n 128 halves],
// row stride 136 halves (272B -> conflict-free LDSM.trans, no swizzle).
#define VSTR 136
__device__ __forceinline__ void mma_chunk_bt(uint32_t aSm, uint32_t vSm,
                                             int m0, int n0, int lane,
                                             float c[2][8][4]) {
    const int lar = lane & 15;
    const int lak = (lane >> 4) * 16;
    const int vr = lane & 15;
    const int vs = (lane >> 4) * 8;
    #pragma unroll
    for (int ks = 0; ks < 4; ++ks) {
        uint32_t a[2][4];
        #pragma unroll
        for (int mt = 0; mt < 2; ++mt)
            ldsm_x4(a[mt][0], a[mt][1], a[mt][2], a[mt][3],
                    aSm + SW128((uint32_t)((m0 + mt*16 + lar)*128 + ks*32 + lak)));
        #pragma unroll
        for (int np = 0; np < 4; ++np) {
            uint32_t b0, b1, b2, b3;
            ldsm_x4t(b0, b1, b2, b3,
                     vSm + (uint32_t)((ks*16 + vr)*(VSTR*2) + (n0 + np*16 + vs)*2));
            mma16816(c[0][np*2    ], a[0], b0, b1);
            mma16816(c[0][np*2 + 1], a[0], b2, b3);
            mma16816(c[1][np*2    ], a[1], b0, b1);
            mma16816(c[1][np*2 + 1], a[1], b2, b3);
        }
    }
}

// ---------------------------------------------------------------------------
// Kernel 1: fused L2-norm + normalize + fp16 pack for Q and K.
// ---------------------------------------------------------------------------
__global__ __launch_bounds__(160) void prep_qk(const float* __restrict__ q,
                                               const float* __restrict__ k) {
    __shared__ float rq[8], rk[8];
    const int row = blockIdx.x;
    const int b = row >> 8, t = row & 255;
    const int tid = threadIdx.x, lane = tid & 31, w = tid >> 5;
    const int base = row_base(b, t);
    float4 qv[5], kv[5];
    float sq = 0.f, sk = 0.f;
    #pragma unroll
    for (int g = 0; g < 5; ++g) {
        const int s = (tid + 160*g) * 4;
        const int a = base + (s >> 7)*NSTRIDE + (s & 127);
        qv[g] = *(const float4*)(q + a);
        kv[g] = *(const float4*)(k + a);
        sq += qv[g].x*qv[g].x + qv[g].y*qv[g].y + qv[g].z*qv[g].z + qv[g].w*qv[g].w;
        sk += kv[g].x*kv[g].x + kv[g].y*kv[g].y + kv[g].z*kv[g].z + kv[g].w*kv[g].w;
    }
    #pragma unroll
    for (int o = 16; o; o >>= 1) {
        sq += __shfl_xor_sync(0xffffffffu, sq, o);
        sk += __shfl_xor_sync(0xffffffffu, sk, o);
    }
    if (lane == 0) { rq[w] = sq; rk[w] = sk; }
    __syncthreads();
    sq = rq[0] + rq[1] + rq[2] + rq[3] + rq[4];
    sk = rk[0] + rk[1] + rk[2] + rk[3] + rk[4];
    const float iq = 1.f / fmaxf(sqrtf(sq), 1e-12f);
    const float ik = 1.f / fmaxf(sqrtf(sk), 1e-12f);
    #pragma unroll
    for (int g = 0; g < 5; ++g) {
        const int s = (tid + 160*g) * 4;
        uint2 uq, uk;
        uq.x = h2u(__floats2half2_rn(qv[g].x*iq, qv[g].y*iq));
        uq.y = h2u(__floats2half2_rn(qv[g].z*iq, qv[g].w*iq));
        uk.x = h2u(__floats2half2_rn(kv[g].x*ik, kv[g].y*ik));
        uk.y = h2u(__floats2half2_rn(kv[g].z*ik, kv[g].w*ik));
        *(uint2*)(g_qh + (size_t)row*SS + s) = uq;
        *(uint2*)(g_kh + (size_t)row*SS + s) = uk;
    }
}

// ---------------------------------------------------------------------------
// Kernel 2: att partial logits, cp.async double-buffered, fp16 mma.sync.
// CTA = (kc, b, tile), tile in {(mh0,nh0),(mh1,nh0),(mh1,nh1)}. Grid 144.
// Dynamic smem 64KB: A0 A1 B0 B1 (16KB each).
// ---------------------------------------------------------------------------
__global__ __launch_bounds__(256, 2) void att_mma() {
    extern __shared__ __align__(128) char sm[];
    int idx = blockIdx.x;
    const int kc = idx / 48; idx %= 48;
    const int b = idx / 3, tt = idx % 3;
    const int t0  = (tt > 0)  ? 128 : 0;
    const int n0c = (tt == 2) ? 128 : 0;
    const int nch = (kc == 2) ? 16 : 17;
    const int sb  = kc * 17 * 64;
    const int tid = threadIdx.x, lane = tid & 31, wid = tid >> 5;
    const int m0 = (wid & 3) * 32, n0w = (wid >> 2) * 64;
    const uint32_t base = smem_u32(sm);

    float c[2][8][4];
    #pragma unroll
    for (int i = 0; i < 2; ++i)
        #pragma unroll
        for (int j = 0; j < 8; ++j)
            #pragma unroll
            for (int e = 0; e < 4; ++e) c[i][j][e] = 0.f;

    const int row = tid >> 1, hf = tid & 1;
    const __half* qp = g_qh + (size_t)(b*256 + t0  + row)*SS + sb + hf*32;
    const __half* kp = g_kh + (size_t)(b*256 + n0c + row)*SS + sb + hf*32;
    uint32_t so[4];
    #pragma unroll
    for (int g = 0; g < 4; ++g) so[g] = SW128((uint32_t)(row*128 + hf*64 + g*16));

    // prologue: chunk 0 -> buffer 0
    #pragma unroll
    for (int g = 0; g < 4; ++g) {
        cp16(base + so[g],         qp + g*8);
        cp16(base + 32768 + so[g], kp + g*8);
    }
    CP_COMMIT();

    for (int it = 0; it < nch; ++it) {
        CP_WAIT0();
        __syncthreads();
        const int nxt = it + 1;
        if (nxt < nch) {
            const uint32_t ab = base + (nxt & 1)*16384;
            #pragma unroll
            for (int g = 0; g < 4; ++g) {
                cp16(ab + so[g],         qp + nxt*64 + g*8);
                cp16(ab + 32768 + so[g], kp + nxt*64 + g*8);
            }
            CP_COMMIT();
        }
        const uint32_t cb = base + (it & 1)*16384;
        mma_chunk(cb, cb + 32768, m0, n0w, lane, c);
    }

    float* dst = g_att_part + (size_t)kc*(4096*256) + (size_t)(b*256 + t0)*256;
    const int r0 = m0 + (lane >> 2);
    const int c0 = n0c + n0w + (lane & 3)*2;
    #pragma unroll
    for (int mt = 0; mt < 2; ++mt)
        #pragma unroll
        for (int n8 = 0; n8 < 8; ++n8) {
            float* p = dst + (size_t)(r0 + mt*16)*256 + c0 + n8*8;
            *(float2*)p           = make_float2(c[mt][n8][0], c[mt][n8][1]);
            *(float2*)(p + 8*256) = make_float2(c[mt][n8][2], c[mt][n8][3]);
        }
}

// ---------------------------------------------------------------------------
// Kernel 3: reduce partials (float4 vectorized), mask, softmax, emit P fp16.
// ---------------------------------------------------------------------------
__global__ __launch_bounds__(256) void softmax_kernel() {
    const int wid = threadIdx.x >> 5, lane = threadIdx.x & 31;
    const int row = blockIdx.x*8 + wid;   // b*256 + t
    const int t = row & 255;
    float4 a[2];
    #pragma unroll
    for (int j2 = 0; j2 < 2; ++j2) {
        float4 s = make_float4(0.f, 0.f, 0.f, 0.f);
        #pragma unroll
        for (int p = 0; p < KCH; ++p) {
            const float4 d = *(const float4*)(g_att_part + (size_t)p*(4096*256)
                                              + (size_t)row*256 + (j2*32 + lane)*4);
            s.x += d.x; s.y += d.y; s.z += d.z; s.w += d.w;
        }
        a[j2] = s;
    }
    float m = -1e30f;
    #pragma unroll
    for (int j2 = 0; j2 < 2; ++j2) {
        const int c0 = (j2*32 + lane)*4;
        float* e = &a[j2].x;
        #pragma unroll
        for (int q = 0; q < 4; ++q) {
            e[q] = (c0 + q <= t) ? e[q] : -1e30f;
            m = fmaxf(m, e[q]);
        }
    }
    #pragma unroll
    for (int o = 16; o; o >>= 1) m = fmaxf(m, __shfl_xor_sync(0xffffffffu, m, o));
    float ssum = 0.f;
    #pragma unroll
    for (int j2 = 0; j2 < 2; ++j2) {
        const int c0 = (j2*32 + lane)*4;
        float* e = &a[j2].x;
        #pragma unroll
        for (int q = 0; q < 4; ++q) {
            e[q] = (c0 + q <= t) ? __expf(e[q] - m) : 0.f;
            ssum += e[q];
        }
    }
    #pragma unroll
    for (int o = 16; o; o >>= 1) ssum += __shfl_xor_sync(0xffffffffu, ssum, o);
    const float inv = 1.f / ssum;
    #pragma unroll
    for (int j2 = 0; j2 < 2; ++j2) {
        uint2 u;
        u.x = h2u(__floats2half2_rn(a[j2].x*inv, a[j2].y*inv));
        u.y = h2u(__floats2half2_rn(a[j2].z*inv, a[j2].w*inv));
        *(uint2*)(g_ph + (size_t)row*256 + (j2*32 + lane)*4) = u;
    }
}

// ---------------------------------------------------------------------------
// Kernel 4: out = P @ V^T + buffer. CTA = (b, mh, st), M=128 t, N=128 s,
// K = 128/256 r. P via cp.async (fp16); V via cp.async fp32 staging + smem
// convert to fp16 [r][s] (VSTR rows); B frags via ldmatrix.trans.
// Dynamic smem: sP[2]x16KB | sVf 32KB | sVh[2]x17408B  = 100352 B.
// ---------------------------------------------------------------------------
#define OFF_VF 32768u
#define OFF_VH 65536u
#define VHB 17408u
__global__ __launch_bounds__(256, 2) void out_mma(const float* __restrict__ v,
                                                  float* __restrict__ out) {
    extern __shared__ __align__(128) char sm[];
    int idx = blockIdx.x;
    const int b = idx / 50; idx %= 50;
    const int mh = 1 - (idx / 25);        // heavy (mh=1) tiles first
    const int st = idx % 25;
    const int t0 = mh*128;
    const int nch = mh ? 4 : 2;
    const int tid = threadIdx.x, lane = tid & 31, wid = tid >> 5;
    const int m0 = (wid & 3) * 32, n0w = (wid >> 2) * 64;
    const uint32_t base = smem_u32(sm);

    float c[2][8][4];
    #pragma unroll
    for (int i = 0; i < 2; ++i)
        #pragma unroll
        for (int j = 0; j < 8; ++j)
            #pragma unroll
            for (int e = 0; e < 4; ++e) c[i][j][e] = 0.f;

    // P: row = tid/2, 32 halves at hf*32 per 64-chunk
    const int row = tid >> 1, hf = tid & 1;
    const __half* ap = g_ph + (size_t)(b*256 + t0 + row)*256 + hf*32;
    uint32_t soA[4];
    #pragma unroll
    for (int g = 0; g < 4; ++g) soA[g] = SW128((uint32_t)(row*128 + hf*64 + g*16));

    // V: rl = tid/4 (0..63), qs = (tid&3)*32; 8x 16B per chunk
    const int rl = tid >> 2, qs = (tid & 3) * 32;
    const float* vp = v + row_base(b, rl) + st*NSTRIDE + qs;   // + ic*64 rows
    const uint32_t vfo = (uint32_t)((rl*128 + qs)*4);

    // prologue: chunk 0
    #pragma unroll
    for (int g = 0; g < 4; ++g) cp16(base + soA[g], ap + g*8);
    #pragma unroll
    for (int g = 0; g < 8; ++g) cp16(base + OFF_VF + vfo + g*16, vp + g*4);
    CP_COMMIT();

    for (int ic = 0; ic < nch; ++ic) {
        CP_WAIT0();
        __syncthreads();
        // convert sVf (fp32 linear) -> sVh[ic&1] (fp16, VSTR rows)
        {
            const uint32_t vh = base + OFF_VH + (uint32_t)(ic & 1)*VHB;
            #pragma unroll
            for (int p = 0; p < 8; ++p) {
                const int f = p*1024 + tid*4;              // float index
                const float4 d = *(const float4*)(sm + OFF_VF + (uint32_t)f*4);
                const int r = f >> 7, s = f & 127;
                uint2 u;
                u.x = h2u(__floats2half2_rn(d.x, d.y));
                u.y = h2u(__floats2half2_rn(d.z, d.w));
                *(uint2*)(sm + (vh - base) + (uint32_t)(r*(VSTR*2) + s*2)) = u;
            }
        }
        __syncthreads();
        const int nxt = ic + 1;
        if (nxt < nch) {
            const uint32_t pb = base + (uint32_t)(nxt & 1)*16384;
            #pragma unroll
            for (int g = 0; g < 4; ++g) cp16(pb + soA[g], ap + nxt*64 + g*8);
            const float* vpn = vp + (size_t)nxt*4*CSTRIDE;   // +64 rows
            #pragma unroll
            for (int g = 0; g < 8; ++g) cp16(base + OFF_VF + vfo + g*16, vpn + g*4);
            CP_COMMIT();
        }
        mma_chunk_bt(base + (uint32_t)(ic & 1)*16384,
                     base + OFF_VH + (uint32_t)(ic & 1)*VHB, m0, n0w, lane, c);
    }

    const int r0 = m0 + (lane >> 2);
    const int sc0 = n0w + (lane & 3)*2;
    const int soff = st*NSTRIDE;
    #pragma unroll
    for (int mt = 0; mt < 2; ++mt) {
        const int tA = t0 + r0 + mt*16;
        const int gA = row_base(b, tA)     + soff;
        const int gB = row_base(b, tA + 8) + soff;
        #pragma unroll
        for (int n8 = 0; n8 < 8; ++n8) {
            const int sc = sc0 + n8*8;
            const float2 buA = *(const float2*)(v + gA + sc);
            const float2 buB = *(const float2*)(v + gB + sc);
            *(float2*)(out + gA + sc) =
                make_float2(c[mt][n8][0] + buA.x, c[mt][n8][1] + buA.y);
            *(float2*)(out + gB + sc) =
                make_float2(c[mt][n8][2] + buB.x, c[mt][n8][3] + buB.y);
        }
    }
}

// ---------------------------------------------------------------------------
#define ATT_SMEM 65536
#define OUT_SMEM 100352

extern "C" void kernel_launch(void* const* d_in, const int* in_sizes, int n_in,
                              void* d_out, int out_size) {
    const float* q = (const float*)d_in[0];
    const float* k = (const float*)d_in[1];
    const float* v = (const float*)d_in[2];
    float* out = (float*)d_out;

    cudaFuncSetAttribute(att_mma, cudaFuncAttributeMaxDynamicSharedMemorySize, ATT_SMEM);
    cudaFuncSetAttribute(out_mma, cudaFuncAttributeMaxDynamicSharedMemorySize, OUT_SMEM);

    prep_qk<<<BB*CH, 160>>>(q, k);
    att_mma<<<KCH*BB*3, 256, ATT_SMEM>>>();
    softmax_kernel<<<BB*CH/8, 256>>>();
    out_mma<<<BB*50, 256, OUT_SMEM>>>(v, out);
}

// round 9
// speedup vs baseline: 6.3316x; 1.0241x over previous
#include <cuda_runtime.h>
#include <cuda_fp16.h>
#include <cstdint>

#define BB 16
#define NN 25
#define WW 128
#define CH 256              // c*h
#define SS 3200             // n*w
#define BSTRIDE 819200
#define CSTRIDE 51200
#define NSTRIDE 2048
#define KCH 3               // K-split chunks in att (17/17/16 x 64)

// Scratch (device globals). Zero-init relied upon: g_att_part tiles for the
// fully-masked (mh0,nh1) region are never written by any launch -> stay 0.
__device__ float g_att_part[KCH*BB*CH*CH];        // 12.6 MB partial logits
__device__ __half g_qh[BB*CH*SS];                 // normalized Q fp16 [row][s]
__device__ __half g_kh[BB*CH*SS];                 // normalized K fp16 [row][s]
__device__ __half g_vh[BB*CH*SS];                 // V fp16 [row][s]
__device__ __half g_ph[BB*CH*CH];                 // P fp16, zeros above diag

__device__ __forceinline__ int row_base(int b, int t) {
    return b*BSTRIDE + (t >> 4)*CSTRIDE + (t & 15)*WW;
}

#define SW128(x) ((x) ^ (((x) >> 3) & 0x70))

__device__ __forceinline__ uint32_t smem_u32(const void* p) {
    uint32_t a;
    asm("{ .reg .u64 t; cvta.to.shared.u64 t, %1; cvt.u32.u64 %0, t; }" : "=r"(a) : "l"(p));
    return a;
}
__device__ __forceinline__ void cp16(uint32_t dst, const void* src) {
    asm volatile("cp.async.cg.shared.global [%0], [%1], 16;"
                 :: "r"(dst), "l"(__cvta_generic_to_global(src)));
}
#define CP_COMMIT() asm volatile("cp.async.commit_group;" ::: "memory")
#define CP_WAIT0()  asm volatile("cp.async.wait_group 0;" ::: "memory")

__device__ __forceinline__ void ldsm_x4(uint32_t& r0, uint32_t& r1,
                                        uint32_t& r2, uint32_t& r3, uint32_t addr) {
    asm volatile("ldmatrix.sync.aligned.m8n8.x4.shared.b16 {%0,%1,%2,%3}, [%4];"
                 : "=r"(r0), "=r"(r1), "=r"(r2), "=r"(r3) : "r"(addr));
}
__device__ __forceinline__ void ldsm_x4t(uint32_t& r0, uint32_t& r1,
                                         uint32_t& r2, uint32_t& r3, uint32_t addr) {
    asm volatile("ldmatrix.sync.aligned.m8n8.x4.trans.shared.b16 {%0,%1,%2,%3}, [%4];"
                 : "=r"(r0), "=r"(r1), "=r"(r2), "=r"(r3) : "r"(addr));
}
__device__ __forceinline__ void mma16816(float* c, const uint32_t* a,
                                         uint32_t b0, uint32_t b1) {
    asm volatile(
        "mma.sync.aligned.m16n8k16.row.col.f32.f16.f16.f32 "
        "{%0,%1,%2,%3}, {%4,%5,%6,%7}, {%8,%9}, {%0,%1,%2,%3};"
        : "+f"(c[0]), "+f"(c[1]), "+f"(c[2]), "+f"(c[3])
        : "r"(a[0]), "r"(a[1]), "r"(a[2]), "r"(a[3]), "r"(b0), "r"(b1));
}
__device__ __forceinline__ uint32_t h2u(__half2 h) {
    return *reinterpret_cast<uint32_t*>(&h);
}

// One 64-wide K chunk, both operands SW128-swizzled [row][64 halves].
__device__ __forceinline__ void mma_chunk(uint32_t aSm, uint32_t bSm,
                                          int m0, int n0, int lane,
                                          float c[2][8][4]) {
    const int lar = lane & 15;
    const int lak = (lane >> 4) * 16;
    const int lbr = (lane & 7) | ((lane >> 4) << 3);
    const int lbk = ((lane >> 3) & 1) * 16;
    #pragma unroll
    for (int ks = 0; ks < 4; ++ks) {
        const int kb = ks * 32;
        uint32_t a[2][4];
        #pragma unroll
        for (int mt = 0; mt < 2; ++mt)
            ldsm_x4(a[mt][0], a[mt][1], a[mt][2], a[mt][3],
                    aSm + SW128((uint32_t)((m0 + mt*16 + lar)*128 + kb + lak)));
        #pragma unroll
        for (int np = 0; np < 4; ++np) {
            uint32_t b0, b1, b2, b3;
            ldsm_x4(b0, b1, b2, b3,
                    bSm + SW128((uint32_t)((n0 + np*16 + lbr)*128 + kb + lbk)));
            mma16816(c[0][np*2    ], a[0], b0, b1);
            mma16816(c[0][np*2 + 1], a[0], b2, b3);
            mma16816(c[1][np*2    ], a[1], b0, b1);
            mma16816(c[1][np*2 + 1], a[1], b2, b3);
        }
    }
}

// One 64-deep K chunk; B (= V) natural [r=k 64 rows][s=n 128 halves],
// row stride 136 halves (272B -> conflict-free LDSM.trans, no swizzle).
#define VSTR 136
__device__ __forceinline__ void mma_chunk_bt(uint32_t aSm, uint32_t vSm,
                                             int m0, int n0, int lane,
                                             float c[2][8][4]) {
    const int lar = lane & 15;
    const int lak = (lane >> 4) * 16;
    const int vr = lane & 15;
    const int vs = (lane >> 4) * 8;
    #pragma unroll
    for (int ks = 0; ks < 4; ++ks) {
        uint32_t a[2][4];
        #pragma unroll
        for (int mt = 0; mt < 2; ++mt)
            ldsm_x4(a[mt][0], a[mt][1], a[mt][2], a[mt][3],
                    aSm + SW128((uint32_t)((m0 + mt*16 + lar)*128 + ks*32 + lak)));
        #pragma unroll
        for (int np = 0; np < 4; ++np) {
            uint32_t b0, b1, b2, b3;
            ldsm_x4t(b0, b1, b2, b3,
                     vSm + (uint32_t)((ks*16 + vr)*(VSTR*2) + (n0 + np*16 + vs)*2));
            mma16816(c[0][np*2    ], a[0], b0, b1);
            mma16816(c[0][np*2 + 1], a[0], b2, b3);
            mma16816(c[1][np*2    ], a[1], b0, b1);
            mma16816(c[1][np*2 + 1], a[1], b2, b3);
        }
    }
}

// ---------------------------------------------------------------------------
// Kernel 1: fused L2-norm + normalize + fp16 pack for Q,K; fp16 convert of V.
// ---------------------------------------------------------------------------
__global__ __launch_bounds__(160) void prep_qk(const float* __restrict__ q,
                                               const float* __restrict__ k,
                                               const float* __restrict__ v) {
    __shared__ float rq[8], rk[8];
    const int row = blockIdx.x;
    const int b = row >> 8, t = row & 255;
    const int tid = threadIdx.x, lane = tid & 31, w = tid >> 5;
    const int base = row_base(b, t);
    float4 qv[5], kv[5];
    float sq = 0.f, sk = 0.f;
    #pragma unroll
    for (int g = 0; g < 5; ++g) {
        const int s = (tid + 160*g) * 4;
        const int a = base + (s >> 7)*NSTRIDE + (s & 127);
        qv[g] = *(const float4*)(q + a);
        kv[g] = *(const float4*)(k + a);
        sq += qv[g].x*qv[g].x + qv[g].y*qv[g].y + qv[g].z*qv[g].z + qv[g].w*qv[g].w;
        sk += kv[g].x*kv[g].x + kv[g].y*kv[g].y + kv[g].z*kv[g].z + kv[g].w*kv[g].w;
    }
    // V convert (independent of norms)
    #pragma unroll
    for (int g = 0; g < 5; ++g) {
        const int s = (tid + 160*g) * 4;
        const int a = base + (s >> 7)*NSTRIDE + (s & 127);
        const float4 vv = *(const float4*)(v + a);
        uint2 uv;
        uv.x = h2u(__floats2half2_rn(vv.x, vv.y));
        uv.y = h2u(__floats2half2_rn(vv.z, vv.w));
        *(uint2*)(g_vh + (size_t)row*SS + s) = uv;
    }
    #pragma unroll
    for (int o = 16; o; o >>= 1) {
        sq += __shfl_xor_sync(0xffffffffu, sq, o);
        sk += __shfl_xor_sync(0xffffffffu, sk, o);
    }
    if (lane == 0) { rq[w] = sq; rk[w] = sk; }
    __syncthreads();
    sq = rq[0] + rq[1] + rq[2] + rq[3] + rq[4];
    sk = rk[0] + rk[1] + rk[2] + rk[3] + rk[4];
    const float iq = 1.f / fmaxf(sqrtf(sq), 1e-12f);
    const float ik = 1.f / fmaxf(sqrtf(sk), 1e-12f);
    #pragma unroll
    for (int g = 0; g < 5; ++g) {
        const int s = (tid + 160*g) * 4;
        uint2 uq, uk;
        uq.x = h2u(__floats2half2_rn(qv[g].x*iq, qv[g].y*iq));
        uq.y = h2u(__floats2half2_rn(qv[g].z*iq, qv[g].w*iq));
        uk.x = h2u(__floats2half2_rn(kv[g].x*ik, kv[g].y*ik));
        uk.y = h2u(__floats2half2_rn(kv[g].z*ik, kv[g].w*ik));
        *(uint2*)(g_qh + (size_t)row*SS + s) = uq;
        *(uint2*)(g_kh + (size_t)row*SS + s) = uk;
    }
}

// ---------------------------------------------------------------------------
// Kernel 2: att partial logits, cp.async double-buffered, fp16 mma.sync.
// CTA = (kc, b, tile), tile in {(mh0,nh0),(mh1,nh0),(mh1,nh1)}. Grid 144.
// Dynamic smem 64KB: A0 A1 B0 B1 (16KB each).
// ---------------------------------------------------------------------------
__global__ __launch_bounds__(256, 2) void att_mma() {
    extern __shared__ __align__(128) char sm[];
    int idx = blockIdx.x;
    const int kc = idx / 48; idx %= 48;
    const int b = idx / 3, tt = idx % 3;
    const int t0  = (tt > 0)  ? 128 : 0;
    const int n0c = (tt == 2) ? 128 : 0;
    const int nch = (kc == 2) ? 16 : 17;
    const int sb  = kc * 17 * 64;
    const int tid = threadIdx.x, lane = tid & 31, wid = tid >> 5;
    const int m0 = (wid & 3) * 32, n0w = (wid >> 2) * 64;
    const uint32_t base = smem_u32(sm);

    float c[2][8][4];
    #pragma unroll
    for (int i = 0; i < 2; ++i)
        #pragma unroll
        for (int j = 0; j < 8; ++j)
            #pragma unroll
            for (int e = 0; e < 4; ++e) c[i][j][e] = 0.f;

    const int row = tid >> 1, hf = tid & 1;
    const __half* qp = g_qh + (size_t)(b*256 + t0  + row)*SS + sb + hf*32;
    const __half* kp = g_kh + (size_t)(b*256 + n0c + row)*SS + sb + hf*32;
    uint32_t so[4];
    #pragma unroll
    for (int g = 0; g < 4; ++g) so[g] = SW128((uint32_t)(row*128 + hf*64 + g*16));

    #pragma unroll
    for (int g = 0; g < 4; ++g) {
        cp16(base + so[g],         qp + g*8);
        cp16(base + 32768 + so[g], kp + g*8);
    }
    CP_COMMIT();

    for (int it = 0; it < nch; ++it) {
        CP_WAIT0();
        __syncthreads();
        const int nxt = it + 1;
        if (nxt < nch) {
            const uint32_t ab = base + (nxt & 1)*16384;
            #pragma unroll
            for (int g = 0; g < 4; ++g) {
                cp16(ab + so[g],         qp + nxt*64 + g*8);
                cp16(ab + 32768 + so[g], kp + nxt*64 + g*8);
            }
            CP_COMMIT();
        }
        const uint32_t cb = base + (it & 1)*16384;
        mma_chunk(cb, cb + 32768, m0, n0w, lane, c);
    }

    float* dst = g_att_part + (size_t)kc*(4096*256) + (size_t)(b*256 + t0)*256;
    const int r0 = m0 + (lane >> 2);
    const int c0 = n0c + n0w + (lane & 3)*2;
    #pragma unroll
    for (int mt = 0; mt < 2; ++mt)
        #pragma unroll
        for (int n8 = 0; n8 < 8; ++n8) {
            float* p = dst + (size_t)(r0 + mt*16)*256 + c0 + n8*8;
            *(float2*)p           = make_float2(c[mt][n8][0], c[mt][n8][1]);
            *(float2*)(p + 8*256) = make_float2(c[mt][n8][2], c[mt][n8][3]);
        }
}

// ---------------------------------------------------------------------------
// Kernel 3: reduce partials (float4 vectorized), mask, softmax, emit P fp16.
// ---------------------------------------------------------------------------
__global__ __launch_bounds__(256) void softmax_kernel() {
    const int wid = threadIdx.x >> 5, lane = threadIdx.x & 31;
    const int row = blockIdx.x*8 + wid;   // b*256 + t
    const int t = row & 255;
    float4 a[2];
    #pragma unroll
    for (int j2 = 0; j2 < 2; ++j2) {
        float4 s = make_float4(0.f, 0.f, 0.f, 0.f);
        #pragma unroll
        for (int p = 0; p < KCH; ++p) {
            const float4 d = *(const float4*)(g_att_part + (size_t)p*(4096*256)
                                              + (size_t)row*256 + (j2*32 + lane)*4);
            s.x += d.x; s.y += d.y; s.z += d.z; s.w += d.w;
        }
        a[j2] = s;
    }
    float m = -1e30f;
    #pragma unroll
    for (int j2 = 0; j2 < 2; ++j2) {
        const int c0 = (j2*32 + lane)*4;
        float* e = &a[j2].x;
        #pragma unroll
        for (int q = 0; q < 4; ++q) {
            e[q] = (c0 + q <= t) ? e[q] : -1e30f;
            m = fmaxf(m, e[q]);
        }
    }
    #pragma unroll
    for (int o = 16; o; o >>= 1) m = fmaxf(m, __shfl_xor_sync(0xffffffffu, m, o));
    float ssum = 0.f;
    #pragma unroll
    for (int j2 = 0; j2 < 2; ++j2) {
        const int c0 = (j2*32 + lane)*4;
        float* e = &a[j2].x;
        #pragma unroll
        for (int q = 0; q < 4; ++q) {
            e[q] = (c0 + q <= t) ? __expf(e[q] - m) : 0.f;
            ssum += e[q];
        }
    }
    #pragma unroll
    for (int o = 16; o; o >>= 1) ssum += __shfl_xor_sync(0xffffffffu, ssum, o);
    const float inv = 1.f / ssum;
    #pragma unroll
    for (int j2 = 0; j2 < 2; ++j2) {
        uint2 u;
        u.x = h2u(__floats2half2_rn(a[j2].x*inv, a[j2].y*inv));
        u.y = h2u(__floats2half2_rn(a[j2].z*inv, a[j2].w*inv));
        *(uint2*)(g_ph + (size_t)row*256 + (j2*32 + lane)*4) = u;
    }
}

// ---------------------------------------------------------------------------
// Kernel 4: out = P @ V^T + buffer. CTA = (b, st): M=256 (all t), N=128 s,
// K=256 (4 chunks). 512 threads, warp grid 8(m) x 2(n). V tile shared by
// both mh halves; P zeros above diag make the result exact. Grid 400.
// smem: P0 P1 (32KB each) | V0 V1 (17KB each, VSTR rows) = 100352 B.
// ---------------------------------------------------------------------------
#define OFF_V0 65536u
#define VHB 17408u
__global__ __launch_bounds__(512) void out_mma(const float* __restrict__ v,
                                               float* __restrict__ out) {
    extern __shared__ __align__(128) char sm[];
    const int b = blockIdx.x / 25, st = blockIdx.x % 25;
    const int tid = threadIdx.x, lane = tid & 31, wid = tid >> 5;
    const int m0 = (wid & 7) * 32, n0w = (wid >> 3) * 64;
    const uint32_t base = smem_u32(sm);

    float c[2][8][4];
    #pragma unroll
    for (int i = 0; i < 2; ++i)
        #pragma unroll
        for (int j = 0; j < 8; ++j)
            #pragma unroll
            for (int e = 0; e < 4; ++e) c[i][j][e] = 0.f;

    // P staging: prow = tid/2 (0..255), half ph = tid&1 (32 halves each)
    const int prow = tid >> 1, ph = tid & 1;
    const __half* ap = g_ph + (size_t)(b*256 + prow)*256 + ph*32;
    uint32_t soP[4];
    #pragma unroll
    for (int g = 0; g < 4; ++g) soP[g] = SW128((uint32_t)(prow*128 + ph*64 + g*16));

    // V staging: vrow = tid/8 (0..63), seg = tid&7 (2 x 16B each)
    const int vrow = tid >> 3, seg = tid & 7;
    const __half* vp = g_vh + (size_t)(b*256 + vrow)*SS + st*128 + seg*16;
    const uint32_t soV = (uint32_t)(vrow*(VSTR*2) + seg*32);

    // prologue: chunk 0
    #pragma unroll
    for (int g = 0; g < 4; ++g) cp16(base + soP[g], ap + g*8);
    cp16(base + OFF_V0 + soV,      vp);
    cp16(base + OFF_V0 + soV + 16, vp + 8);
    CP_COMMIT();

    #pragma unroll
    for (int ic = 0; ic < 4; ++ic) {
        CP_WAIT0();
        __syncthreads();
        const int nxt = ic + 1;
        if (nxt < 4) {
            const uint32_t pb = base + (uint32_t)(nxt & 1)*32768u;
            #pragma unroll
            for (int g = 0; g < 4; ++g) cp16(pb + soP[g], ap + nxt*64 + g*8);
            const uint32_t vb = base + OFF_V0 + (uint32_t)(nxt & 1)*VHB;
            const __half* vpn = vp + (size_t)nxt*64*SS;
            cp16(vb + soV,      vpn);
            cp16(vb + soV + 16, vpn + 8);
            CP_COMMIT();
        }
        mma_chunk_bt(base + (uint32_t)(ic & 1)*32768u,
                     base + OFF_V0 + (uint32_t)(ic & 1)*VHB, m0, n0w, lane, c);
    }

    const int r0 = m0 + (lane >> 2);
    const int sc0 = n0w + (lane & 3)*2;
    const int soff = st*NSTRIDE;
    #pragma unroll
    for (int mt = 0; mt < 2; ++mt) {
        const int tA = r0 + mt*16;
        const int gA = row_base(b, tA)     + soff;
        const int gB = row_base(b, tA + 8) + soff;
        #pragma unroll
        for (int n8 = 0; n8 < 8; ++n8) {
            const int sc = sc0 + n8*8;
            const float2 buA = *(const float2*)(v + gA + sc);
            const float2 buB = *(const float2*)(v + gB + sc);
            *(float2*)(out + gA + sc) =
                make_float2(c[mt][n8][0] + buA.x, c[mt][n8][1] + buA.y);
            *(float2*)(out + gB + sc) =
                make_float2(c[mt][n8][2] + buB.x, c[mt][n8][3] + buB.y);
        }
    }
}

// ---------------------------------------------------------------------------
#define ATT_SMEM 65536
#define OUT_SMEM 100352

extern "C" void kernel_launch(void* const* d_in, const int* in_sizes, int n_in,
                              void* d_out, int out_size) {
    const float* q = (const float*)d_in[0];
    const float* k = (const float*)d_in[1];
    const float* v = (const float*)d_in[2];
    float* out = (float*)d_out;

    cudaFuncSetAttribute(att_mma, cudaFuncAttributeMaxDynamicSharedMemorySize, ATT_SMEM);
    cudaFuncSetAttribute(out_mma, cudaFuncAttributeMaxDynamicSharedMemorySize, OUT_SMEM);

    prep_qk<<<BB*CH, 160>>>(q, k, v);
    att_mma<<<KCH*BB*3, 256, ATT_SMEM>>>();
    softmax_kernel<<<BB*CH/8, 256>>>();
    out_mma<<<BB*NN, 512, OUT_SMEM>>>(v, out);
}